// round 11
// baseline (speedup 1.0000x reference)
#include <cuda_runtime.h>
#include <cuda_bf16.h>
#include <math.h>
#include <stdint.h>

#define N      8192
#define D      128
#define NCLS   128
#define NCHUNK 32            // N/256 (label chunks)
#define TT     128           // gram tile (rows == cols)
#define NT     (N / TT)      // 64 tiles per dim
#define NBLK   1056          // sum over rt of ceil((64-rt)/2)
#define CAP    128           // max class size supported
#define LDAB   272           // bytes per smem tile row: 128 bf16 + 8 pad
#define SSTR   132           // S matrix row stride (floats)
#define LN2F   0.6931471805599453f

// ---------------- scratch (device globals; no allocations) ----------------
__device__ __nv_bfloat16  g_yhi[N * D];        // bf16(x * invn * sqrt(log2e/T))
__device__ float          g_rowTot[N];         // accumulated via atomicAdd (zeroed in prep)
__device__ int            g_ofs[NCLS + 1];
__device__ int            g_cntG[NCHUNK][NCLS];
__device__ int            g_order[N];
__device__ float          g_classLoss[2 * NCLS];
__device__ int            g_done;              // class_loss last-block counter
__device__ int            g_sync1, g_sync2;    // ofs_scatter spin barrier (self-reset)

// ---------------- helpers ----------------
__device__ __forceinline__ uint32_t smem_u32(const void* p) {
    uint32_t a;
    asm("{ .reg .u64 t; cvta.to.shared.u64 t, %1; cvt.u32.u64 %0, t; }" : "=r"(a) : "l"(p));
    return a;
}
__device__ __forceinline__ float ex2f(float x) {
    float r;
    asm("ex2.approx.ftz.f32 %0, %1;" : "=f"(r) : "f"(x));
    return r;
}
__device__ __forceinline__ float lg2f(float x) {
    float r;
    asm("lg2.approx.f32 %0, %1;" : "=f"(r) : "f"(x));
    return r;
}
__device__ __forceinline__ void cpa16(uint32_t dst, const void* src) {
    asm volatile("{ .reg .u64 g; cvta.to.global.u64 g, %1; cp.async.cg.shared.global [%0], [g], 16; }"
                 :: "r"(dst), "l"(src) : "memory");
}
#define CPA_COMMIT()  asm volatile("cp.async.commit_group;" ::: "memory")
#define CPA_WAIT0()   asm volatile("cp.async.wait_group 0;" ::: "memory")

#define LDSM4(r, addr)                                                           \
    asm volatile("ldmatrix.sync.aligned.m8n8.x4.shared.b16 {%0,%1,%2,%3}, [%4];" \
        : "=r"((r)[0]), "=r"((r)[1]), "=r"((r)[2]), "=r"((r)[3]) : "r"(addr))

#define MMA16816(d, a, b0r, b1r)                                                 \
    asm volatile("mma.sync.aligned.m16n8k16.row.col.f32.bf16.bf16.f32 "          \
        "{%0,%1,%2,%3}, {%4,%5,%6,%7}, {%8,%9}, {%0,%1,%2,%3};"                  \
        : "+f"((d)[0]), "+f"((d)[1]), "+f"((d)[2]), "+f"((d)[3])                 \
        : "r"((a)[0]), "r"((a)[1]), "r"((a)[2]), "r"((a)[3]), "r"(b0r), "r"(b1r))

// ---------------- 1) fused norms + prescale + bf16 + rowTot zero ----------------
__global__ void prep_kernel(const float* __restrict__ x) {
    int row  = blockIdx.x * 8 + (threadIdx.x >> 5);
    int lane = threadIdx.x & 31;
    float4 v = *(const float4*)(x + (size_t)row * D + lane * 4);
    float ss = v.x * v.x + v.y * v.y + v.z * v.z + v.w * v.w;
    #pragma unroll
    for (int o = 16; o > 0; o >>= 1) ss += __shfl_xor_sync(0xffffffffu, ss, o);
    float s = rsqrtf(fmaxf(ss, 1e-12f)) * 2.6858190963521055f;  // invn*sqrt(log2e/T)
    __nv_bfloat162 p0(__float2bfloat16(v.x * s), __float2bfloat16(v.y * s));
    __nv_bfloat162 p1(__float2bfloat16(v.z * s), __float2bfloat16(v.w * s));
    uint2 pk;
    pk.x = *(uint32_t*)&p0;
    pk.y = *(uint32_t*)&p1;
    *(uint2*)(g_yhi + (size_t)row * D + lane * 4) = pk;
    if (lane == 0) g_rowTot[row] = 0.f;   // stream-ordered before gram's atomics
}

// ---------------- 2) fused offsets + stable scatter (32 blocks, spin barrier) ----------------
__global__ void ofs_scatter_kernel(const int* __restrict__ label) {
    __shared__ int myCnt[NCLS];
    __shared__ int all[NCHUNK][NCLS];   // 16 KB
    __shared__ int chunkBase[NCLS];
    __shared__ int wsum[4];
    __shared__ int wcnt[8][NCLS];
    const int t = threadIdx.x, blk = blockIdx.x;
    const int w = t >> 5, lane = t & 31;

    // (a) histogram my 256-row chunk
    if (t < NCLS) myCnt[t] = 0;
    __syncthreads();
    const int gi = blk * 256 + t;
    const int c = label[gi];
    atomicAdd(&myCnt[c], 1);
    __syncthreads();
    if (t < NCLS) g_cntG[blk][t] = myCnt[t];

    // (b) publish + spin until all 32 chunks published (all blocks co-resident)
    __threadfence();
    __syncthreads();
    if (t == 0) {
        atomicAdd(&g_sync1, 1);
        while (atomicAdd(&g_sync1, 0) < NCHUNK) {}
    }
    __syncthreads();
    __threadfence();

    // (c) every block loads all counts, computes identical class scan + its bases
    for (int i = t; i < NCHUNK * NCLS; i += 256) (&all[0][0])[i] = (&g_cntG[0][0])[i];
    __syncthreads();
    if (t < NCLS) {
        int tot = 0, part = 0;
        #pragma unroll
        for (int k = 0; k < NCHUNK; k++) { int v = all[k][t]; tot += v; if (k < blk) part += v; }
        // exclusive scan of tot over classes: warp scan + warp-offset fixup
        int inc = tot;
        #pragma unroll
        for (int o = 1; o < 32; o <<= 1) {
            int u = __shfl_up_sync(0xffffffffu, inc, o);
            if (lane >= o) inc += u;
        }
        if (lane == 31) wsum[w] = inc;
        __syncwarp();
        // (fixup after barrier below)
        chunkBase[t] = inc - tot + part;   // partial: missing warp offsets
    }
    __syncthreads();
    if (t < NCLS) {
        int wo = 0;
        #pragma unroll
        for (int k = 0; k < 4; k++) if (k < w) wo += wsum[k];
        chunkBase[t] += wo;
        if (blk == 0) {
            g_ofs[t] = chunkBase[t] - 0;   // note: for blk==0 part==0 -> this is ofs[t]
            if (t == NCLS - 1) g_ofs[NCLS] = N;
        }
    }
    __syncthreads();

    // (d) ballot-rank stable scatter within my chunk
    for (int i = t; i < 8 * NCLS; i += 256) (&wcnt[0][0])[i] = 0;
    __syncthreads();
    unsigned mask = __match_any_sync(0xffffffffu, c);
    int rankInWarp = __popc(mask & ((1u << lane) - 1u));
    if (lane == (__ffs(mask) - 1)) wcnt[w][c] = __popc(mask);
    __syncthreads();
    int before = 0;
    for (int w2 = 0; w2 < w; w2++) before += wcnt[w2][c];
    g_order[chunkBase[c] + before + rankInWarp] = gi;

    // (e) reset spin counters for next graph replay
    __syncthreads();
    if (t == 0) {
        if (atomicAdd(&g_sync2, 1) == NCHUNK - 1) { g_sync1 = 0; g_sync2 = 0; }
    }
}

// ---------------- 3) HMMA Gram: tile pairs, direct atomic reductions ----------------
#define SM_A     0
#define SM_B0    34816
#define SM_B1    69632
#define SM_TOTAL 104448                 // 3 tiles; occupancy is register-limited anyway

__device__ __forceinline__ void stage_tile(uint32_t dstBase, int rowStart, int tid) {
    for (int i = tid; i < 128 * 16; i += 256) {
        int r = i >> 4, c8 = i & 15;
        cpa16(dstBase + (uint32_t)r * LDAB + (uint32_t)c8 * 16,
              g_yhi + (size_t)(rowStart + r) * D + c8 * 8);
    }
}

__global__ void __launch_bounds__(256, 2) gram_hmma() {
    extern __shared__ char smem[];
    const uint32_t sb = smem_u32(smem);
    const int tid = threadIdx.x, wid = tid >> 5, lane = tid & 31;

    // decode block -> (rt strip, pair of column tiles starting at ct0)
    int b = blockIdx.x, rt = 0;
    for (;;) { int nc = (NT - rt + 1) >> 1; if (b < nc) break; b -= nc; rt++; }
    const int ct0 = rt + b * 2;
    const int ctEnd = (ct0 + 2 < NT) ? (ct0 + 2) : NT;
    const int rowBase = rt * TT;

    stage_tile(sb + SM_A, rowBase, tid);
    if (ct0 != rt) stage_tile(sb + SM_B0, ct0 * TT, tid);
    CPA_COMMIT();
    CPA_WAIT0();
    __syncthreads();

    const int wy = wid & 3, wx = wid >> 2;      // warp grid 4(M) x 2(N)
    const int aRow = wy * 32, bRow = wx * 64;
    const int aR  = aRow + (lane & 15);
    const int aC  = (lane >> 4) * 16;
    const int bR  = bRow + (lane & 7) + ((lane >> 4) << 3);
    const int bC  = ((lane >> 3) & 1) * 16;
    const int g = lane >> 2, t4 = lane & 3;

    float rsum[2][2] = {{0.f, 0.f}, {0.f, 0.f}};      // accumulates across the pair

    for (int ct = ct0; ct < ctEnd; ct++) {
        const uint32_t bbase = (ct == rt) ? SM_A : (((ct - ct0) & 1) ? SM_B1 : SM_B0);
        const bool pre = (ct + 1 < ctEnd);
        if (pre) {   // prefetch next B while computing this tile
            stage_tile(sb + (((ct + 1 - ct0) & 1) ? SM_B1 : SM_B0), (ct + 1) * TT, tid);
            CPA_COMMIT();
        }

        float acc[2][8][4];
        #pragma unroll
        for (int mi = 0; mi < 2; mi++)
            #pragma unroll
            for (int nt = 0; nt < 8; nt++)
                #pragma unroll
                for (int q = 0; q < 4; q++) acc[mi][nt][q] = 0.f;

        #pragma unroll
        for (int kk = 0; kk < 8; kk++) {
            const uint32_t kOff = (uint32_t)kk * 32;
            uint32_t ah[2][4], bh[4][4];
            #pragma unroll
            for (int mi = 0; mi < 2; mi++)
                LDSM4(ah[mi], sb + SM_A + (uint32_t)(aR + mi * 16) * LDAB + kOff + aC);
            #pragma unroll
            for (int ni = 0; ni < 4; ni++)
                LDSM4(bh[ni], sb + bbase + (uint32_t)(bR + ni * 16) * LDAB + kOff + bC);
            #pragma unroll
            for (int mi = 0; mi < 2; mi++)
                #pragma unroll
                for (int ni = 0; ni < 4; ni++)
                    #pragma unroll
                    for (int h = 0; h < 2; h++)
                        MMA16816(acc[mi][ni * 2 + h], ah[mi], bh[ni][h * 2], bh[ni][h * 2 + 1]);
        }

        if (ct != rt) {
            // off-diagonal: row sums (registers) + column sums (direct atomics)
            float cs[8][2];
            #pragma unroll
            for (int nt = 0; nt < 8; nt++) { cs[nt][0] = 0.f; cs[nt][1] = 0.f; }
            #pragma unroll
            for (int mi = 0; mi < 2; mi++)
                #pragma unroll
                for (int nt = 0; nt < 8; nt++) {
                    float e0 = ex2f(acc[mi][nt][0]);
                    float e1 = ex2f(acc[mi][nt][1]);
                    float e2 = ex2f(acc[mi][nt][2]);
                    float e3 = ex2f(acc[mi][nt][3]);
                    rsum[mi][0] += e0 + e1;
                    rsum[mi][1] += e2 + e3;
                    cs[nt][0] += e0 + e2;
                    cs[nt][1] += e1 + e3;
                }
            #pragma unroll
            for (int nt = 0; nt < 8; nt++)
                #pragma unroll
                for (int sc = 0; sc < 2; sc++) {
                    float s = cs[nt][sc];
                    s += __shfl_xor_sync(0xffffffffu, s, 4);
                    s += __shfl_xor_sync(0xffffffffu, s, 8);
                    s += __shfl_xor_sync(0xffffffffu, s, 16);
                    if (g == 0)   // lanes 0-3 hold col sums; 4 wy-warps combine via atomics
                        atomicAdd(&g_rowTot[ct * TT + bRow + nt * 8 + t4 * 2 + sc], s);
                }
        } else {
            // diagonal tile: mask the diagonal; no column sums
            #pragma unroll
            for (int mi = 0; mi < 2; mi++) {
                const int row0 = aRow + mi * 16 + g;
                const int row1 = row0 + 8;
                #pragma unroll
                for (int nt = 0; nt < 8; nt++) {
                    const int gc = bRow + nt * 8 + t4 * 2;
                    float e0 = (row0 == gc    ) ? 0.f : ex2f(acc[mi][nt][0]);
                    float e1 = (row0 == gc + 1) ? 0.f : ex2f(acc[mi][nt][1]);
                    float e2 = (row1 == gc    ) ? 0.f : ex2f(acc[mi][nt][2]);
                    float e3 = (row1 == gc + 1) ? 0.f : ex2f(acc[mi][nt][3]);
                    rsum[mi][0] += e0 + e1;
                    rsum[mi][1] += e2 + e3;
                }
            }
        }
        if (pre) {
            CPA_WAIT0();
            __syncthreads();   // B buffer rotation only
        }
    }

    // pair-accumulated row sums -> direct atomics (2 wx-warps combine per row)
    #pragma unroll
    for (int mi = 0; mi < 2; mi++)
        #pragma unroll
        for (int hrow = 0; hrow < 2; hrow++) {
            float s = rsum[mi][hrow];
            s += __shfl_xor_sync(0xffffffffu, s, 1);
            s += __shfl_xor_sync(0xffffffffu, s, 2);
            if (t4 == 0)
                atomicAdd(&g_rowTot[rowBase + aRow + mi * 16 + hrow * 8 + g], s);
        }
}

// ---------------- 4) per-class loss: 2 blocks/class, HMMA half-Gram ----------------
#define CLS_SMEM (128 * LDAB + 64 * SSTR * 4)    // 34816 + 33792 = 68608
__global__ void __launch_bounds__(256, 2) class_loss_kernel(float* __restrict__ out) {
    extern __shared__ char cs_[];
    char*  tile = cs_;
    float* S    = (float*)(cs_ + 128 * LDAB);    // [64][SSTR]
    __shared__ int   gidx[CAP];
    __shared__ float unsimS[64];
    __shared__ float tr[256];
    __shared__ int   isLast;
    const uint32_t sb = smem_u32(tile);
    const int c = blockIdx.x >> 1, half = blockIdx.x & 1;
    const int tid = threadIdx.x, wid = tid >> 5, lane = tid & 31;
    const int base = g_ofs[c];
    int n = g_ofs[c + 1] - base;
    if (n > CAP) n = CAP;
    const int rows0 = half * 64;                 // this block's row range [rows0, rows0+64)

    for (int i = tid; i < CAP; i += 256) gidx[i] = (i < n) ? g_order[base + i] : 0;
    __syncthreads();
    for (int i = tid; i < 128 * 16; i += 256) {
        int r = i >> 4, c8 = i & 15;
        uint32_t off = (uint32_t)r * LDAB + (uint32_t)c8 * 16;
        uint4 v = make_uint4(0u, 0u, 0u, 0u);
        if (r < n) v = ((const uint4*)(g_yhi + (size_t)gidx[r] * D))[c8];
        *(uint4*)(tile + off) = v;
    }
    __syncthreads();

    // half-Gram: rows [rows0, rows0+64) x cols [0,128); warp grid 2(M) x 4(N)
    const int wy = wid & 1, wx = wid >> 1;
    const int aRow = rows0 + wy * 32, bRow = wx * 32;
    const int aR  = aRow + (lane & 15);
    const int aC  = (lane >> 4) * 16;
    const int bR  = bRow + (lane & 7) + ((lane >> 4) << 3);
    const int bC  = ((lane >> 3) & 1) * 16;

    float acc[2][4][4];
    #pragma unroll
    for (int mi = 0; mi < 2; mi++)
        #pragma unroll
        for (int nt = 0; nt < 4; nt++)
            #pragma unroll
            for (int q = 0; q < 4; q++) acc[mi][nt][q] = 0.f;

    #pragma unroll
    for (int kk = 0; kk < 8; kk++) {
        const uint32_t kOff = (uint32_t)kk * 32;
        uint32_t ah[2][4], bh[2][4];
        #pragma unroll
        for (int mi = 0; mi < 2; mi++)
            LDSM4(ah[mi], sb + (uint32_t)(aR + mi * 16) * LDAB + kOff + aC);
        #pragma unroll
        for (int ni = 0; ni < 2; ni++)
            LDSM4(bh[ni], sb + (uint32_t)(bR + ni * 16) * LDAB + kOff + bC);
        #pragma unroll
        for (int mi = 0; mi < 2; mi++)
            #pragma unroll
            for (int ni = 0; ni < 2; ni++)
                #pragma unroll
                for (int h = 0; h < 2; h++)
                    MMA16816(acc[mi][ni * 2 + h], ah[mi], bh[ni][h * 2], bh[ni][h * 2 + 1]);
    }

    // store S (local rows 0..63) — s = log2-domain sim/T
    const int g = lane >> 2, t4 = lane & 3;
    #pragma unroll
    for (int mi = 0; mi < 2; mi++) {
        const int r0 = wy * 32 + mi * 16 + g;    // local row
        #pragma unroll
        for (int nt = 0; nt < 4; nt++) {
            const int col = bRow + nt * 8 + t4 * 2;
            *(float2*)&S[r0 * SSTR + col]       = make_float2(acc[mi][nt][0], acc[mi][nt][1]);
            *(float2*)&S[(r0 + 8) * SSTR + col] = make_float2(acc[mi][nt][2], acc[mi][nt][3]);
        }
    }
    __syncthreads();

    // possum -> unsim for this block's rows
    for (int i = wid; i < 64; i += 8) {
        const int m = rows0 + i;                 // global member index
        if (m >= n) break;
        float ps = 0.f;
        for (int j = lane; j < n; j += 32)
            if (j != m) ps += ex2f(S[i * SSTR + j]);
        #pragma unroll
        for (int o = 16; o > 0; o >>= 1) ps += __shfl_xor_sync(0xffffffffu, ps, o);
        if (lane == 0) unsimS[i] = g_rowTot[gidx[m]] - ps;
    }
    __syncthreads();

    // loss terms for this block's rows
    float la = 0.f;
    const int nrows = (n - rows0 < 64) ? (n - rows0) : 64;
    if (nrows > 0) {
        const int nn = nrows * n;
        for (int p = tid; p < nn; p += 256) {
            int i = p / n, j = p - i * n;
            if (rows0 + i == j) continue;
            float s = S[i * SSTR + j];
            la += lg2f(ex2f(s) + unsimS[i]) - s;
        }
    }
    tr[tid] = la * LN2F;
    __syncthreads();
    #pragma unroll
    for (int o = 128; o > 0; o >>= 1) {
        if (tid < o) tr[tid] += tr[tid + o];
        __syncthreads();
    }
    if (tid == 0) {
        g_classLoss[blockIdx.x] = tr[0];
        __threadfence();
        isLast = (atomicAdd(&g_done, 1) == 2 * NCLS - 1);
    }
    __syncthreads();
    if (isLast) {
        __threadfence();
        if (tid == 0) {
            float L = 0.f, P = 0.f;
            for (int k = 0; k < 2 * NCLS; k++) L += g_classLoss[k];
            for (int k = 0; k < NCLS; k++) {
                float nc = (float)(g_ofs[k + 1] - g_ofs[k]);
                P += nc * (nc - 1.f);
            }
            out[0] = L / P;
            g_done = 0;   // reset for next graph replay
        }
    }
}

// ---------------- launch ----------------
extern "C" void kernel_launch(void* const* d_in, const int* in_sizes, int n_in,
                              void* d_out, int out_size) {
    const float* x     = (const float*)d_in[0];
    const int*   label = (const int*)d_in[1];
    float*       out   = (float*)d_out;

    cudaFuncSetAttribute(gram_hmma, cudaFuncAttributeMaxDynamicSharedMemorySize, SM_TOTAL);
    cudaFuncSetAttribute(class_loss_kernel, cudaFuncAttributeMaxDynamicSharedMemorySize, CLS_SMEM);

    prep_kernel<<<N / 8, 256>>>(x);
    ofs_scatter_kernel<<<NCHUNK, 256>>>(label);
    gram_hmma<<<NBLK, 256, SM_TOTAL>>>();
    class_loss_kernel<<<2 * NCLS, 256, CLS_SMEM>>>(out);
}

// round 12
// speedup vs baseline: 1.2216x; 1.2216x over previous
#include <cuda_runtime.h>
#include <cuda_bf16.h>
#include <math.h>
#include <stdint.h>

#define N      8192
#define D      128
#define NCLS   128
#define NCHUNK 32            // N/256 (label chunks)
#define TT     128           // gram tile (rows == cols)
#define NT     (N / TT)      // 64 tiles per dim
#define NBLK   1056          // sum over rt of ceil((64-rt)/2)
#define CAP    128           // max class size supported
#define LDAB   272           // bytes per smem tile row: 128 bf16 + 8 pad
#define SSTR   132           // S matrix row stride (floats)
#define LN2F   0.6931471805599453f

// ---------------- scratch (device globals; no allocations) ----------------
__device__ __nv_bfloat16  g_yhi[N * D];        // bf16(x * invn * sqrt(log2e/T))
__device__ float          g_rowTot[N];         // accumulated via atomicAdd (zeroed in prep)
__device__ int            g_ofs[NCLS + 1];
__device__ int            g_chunkBase[NCHUNK][NCLS];
__device__ int            g_order[N];
__device__ float          g_classLoss[NCLS];
__device__ int            g_done;              // class_loss last-block counter

// ---------------- helpers ----------------
__device__ __forceinline__ uint32_t smem_u32(const void* p) {
    uint32_t a;
    asm("{ .reg .u64 t; cvta.to.shared.u64 t, %1; cvt.u32.u64 %0, t; }" : "=r"(a) : "l"(p));
    return a;
}
__device__ __forceinline__ float ex2f(float x) {
    float r;
    asm("ex2.approx.ftz.f32 %0, %1;" : "=f"(r) : "f"(x));
    return r;
}
__device__ __forceinline__ float lg2f(float x) {
    float r;
    asm("lg2.approx.f32 %0, %1;" : "=f"(r) : "f"(x));
    return r;
}
__device__ __forceinline__ void cpa16(uint32_t dst, const void* src) {
    asm volatile("{ .reg .u64 g; cvta.to.global.u64 g, %1; cp.async.cg.shared.global [%0], [g], 16; }"
                 :: "r"(dst), "l"(src) : "memory");
}
#define CPA_COMMIT()  asm volatile("cp.async.commit_group;" ::: "memory")
#define CPA_WAIT0()   asm volatile("cp.async.wait_group 0;" ::: "memory")

#define LDSM4(r, addr)                                                           \
    asm volatile("ldmatrix.sync.aligned.m8n8.x4.shared.b16 {%0,%1,%2,%3}, [%4];" \
        : "=r"((r)[0]), "=r"((r)[1]), "=r"((r)[2]), "=r"((r)[3]) : "r"(addr))

#define MMA16816(d, a, b0r, b1r)                                                 \
    asm volatile("mma.sync.aligned.m16n8k16.row.col.f32.bf16.bf16.f32 "          \
        "{%0,%1,%2,%3}, {%4,%5,%6,%7}, {%8,%9}, {%0,%1,%2,%3};"                  \
        : "+f"((d)[0]), "+f"((d)[1]), "+f"((d)[2]), "+f"((d)[3])                 \
        : "r"((a)[0]), "r"((a)[1]), "r"((a)[2]), "r"((a)[3]), "r"(b0r), "r"(b1r))

// ---------------- 1) fused norms + prescale + bf16 + rowTot zero ----------------
__global__ void prep_kernel(const float* __restrict__ x) {
    int row  = blockIdx.x * 8 + (threadIdx.x >> 5);
    int lane = threadIdx.x & 31;
    float4 v = *(const float4*)(x + (size_t)row * D + lane * 4);
    float ss = v.x * v.x + v.y * v.y + v.z * v.z + v.w * v.w;
    #pragma unroll
    for (int o = 16; o > 0; o >>= 1) ss += __shfl_xor_sync(0xffffffffu, ss, o);
    float s = rsqrtf(fmaxf(ss, 1e-12f)) * 2.6858190963521055f;  // invn*sqrt(log2e/T)
    __nv_bfloat162 p0(__float2bfloat16(v.x * s), __float2bfloat16(v.y * s));
    __nv_bfloat162 p1(__float2bfloat16(v.z * s), __float2bfloat16(v.w * s));
    uint2 pk;
    pk.x = *(uint32_t*)&p0;
    pk.y = *(uint32_t*)&p1;
    *(uint2*)(g_yhi + (size_t)row * D + lane * 4) = pk;
    if (lane == 0) g_rowTot[row] = 0.f;   // stream-ordered before gram's atomics
}

// ---------------- 2) class offsets (deterministic) ----------------
__global__ void build_ofs_kernel(const int* __restrict__ label) {
    __shared__ int cnt[NCHUNK][NCLS];
    __shared__ int tot[NCLS];
    __shared__ int ofs[NCLS];
    int t = threadIdx.x;
    for (int i = t; i < NCHUNK * NCLS; i += 256) (&cnt[0][0])[i] = 0;
    __syncthreads();
    for (int i = t; i < N; i += 256) atomicAdd(&cnt[i >> 8][label[i]], 1);
    __syncthreads();
    if (t < NCLS) {
        int run = 0;
        #pragma unroll
        for (int k = 0; k < NCHUNK; k++) { int v = cnt[k][t]; cnt[k][t] = run; run += v; }
        tot[t] = run;
    }
    __syncthreads();
    if (t == 0) {
        int run = 0;
        for (int c = 0; c < NCLS; c++) { ofs[c] = run; g_ofs[c] = run; run += tot[c]; }
        g_ofs[NCLS] = run;
    }
    __syncthreads();
    if (t < NCLS)
        #pragma unroll
        for (int k = 0; k < NCHUNK; k++) g_chunkBase[k][t] = ofs[t] + cnt[k][t];
}

// ---------------- 3) stable scatter (ballot rank, parallel) ----------------
__global__ void scatter_kernel(const int* __restrict__ label) {
    __shared__ int wcnt[8][NCLS];
    const int t = threadIdx.x, w = t >> 5, lane = t & 31;
    for (int i = t; i < 8 * NCLS; i += 256) (&wcnt[0][0])[i] = 0;
    __syncthreads();
    const int gi = blockIdx.x * 256 + t;
    const int c = label[gi];
    unsigned mask = __match_any_sync(0xffffffffu, c);
    int rankInWarp = __popc(mask & ((1u << lane) - 1u));
    if (lane == (__ffs(mask) - 1)) wcnt[w][c] = __popc(mask);
    __syncthreads();
    int before = 0;
    for (int w2 = 0; w2 < w; w2++) before += wcnt[w2][c];
    g_order[g_chunkBase[blockIdx.x][c] + before + rankInWarp] = gi;
}

// ---------------- 4) HMMA Gram: tile pairs, smem-reduced + atomic rowTot (R10) ----------------
#define SM_A     0
#define SM_B0    34816
#define SM_B1    69632
#define SM_RED   104448                 // red 1KB + colRed 2KB
#define SM_TOTAL (SM_RED + 3072)        // 107520 B -> 2 CTAs/SM

__device__ __forceinline__ void stage_tile(uint32_t dstBase, int rowStart, int tid) {
    for (int i = tid; i < 128 * 16; i += 256) {
        int r = i >> 4, c8 = i & 15;
        cpa16(dstBase + (uint32_t)r * LDAB + (uint32_t)c8 * 16,
              g_yhi + (size_t)(rowStart + r) * D + c8 * 8);
    }
}

__global__ void __launch_bounds__(256, 2) gram_hmma() {
    extern __shared__ char smem[];
    const uint32_t sb = smem_u32(smem);
    const int tid = threadIdx.x, wid = tid >> 5, lane = tid & 31;

    // decode block -> (rt strip, pair of column tiles starting at ct0)
    int b = blockIdx.x, rt = 0;
    for (;;) { int nc = (NT - rt + 1) >> 1; if (b < nc) break; b -= nc; rt++; }
    const int ct0 = rt + b * 2;
    const int ctEnd = (ct0 + 2 < NT) ? (ct0 + 2) : NT;
    const int rowBase = rt * TT;

    stage_tile(sb + SM_A, rowBase, tid);
    if (ct0 != rt) stage_tile(sb + SM_B0, ct0 * TT, tid);
    CPA_COMMIT();
    CPA_WAIT0();
    __syncthreads();

    const int wy = wid & 3, wx = wid >> 2;      // warp grid 4(M) x 2(N)
    const int aRow = wy * 32, bRow = wx * 64;
    const int aR  = aRow + (lane & 15);
    const int aC  = (lane >> 4) * 16;
    const int bR  = bRow + (lane & 7) + ((lane >> 4) << 3);
    const int bC  = ((lane >> 3) & 1) * 16;
    const int g = lane >> 2, t4 = lane & 3;

    float* red    = (float*)(smem + SM_RED);          // [128][2 wx]
    float* colRed = (float*)(smem + SM_RED + 1024);   // [128][4 wy]

    float rsum[2][2] = {{0.f, 0.f}, {0.f, 0.f}};      // accumulates across the pair

    for (int ct = ct0; ct < ctEnd; ct++) {
        const uint32_t bbase = (ct == rt) ? SM_A : (((ct - ct0) & 1) ? SM_B1 : SM_B0);
        const bool pre = (ct + 1 < ctEnd);
        if (pre) {   // prefetch next B while computing this tile
            stage_tile(sb + (((ct + 1 - ct0) & 1) ? SM_B1 : SM_B0), (ct + 1) * TT, tid);
            CPA_COMMIT();
        }

        float acc[2][8][4];
        #pragma unroll
        for (int mi = 0; mi < 2; mi++)
            #pragma unroll
            for (int nt = 0; nt < 8; nt++)
                #pragma unroll
                for (int q = 0; q < 4; q++) acc[mi][nt][q] = 0.f;

        #pragma unroll
        for (int kk = 0; kk < 8; kk++) {
            const uint32_t kOff = (uint32_t)kk * 32;
            uint32_t ah[2][4], bh[4][4];
            #pragma unroll
            for (int mi = 0; mi < 2; mi++)
                LDSM4(ah[mi], sb + SM_A + (uint32_t)(aR + mi * 16) * LDAB + kOff + aC);
            #pragma unroll
            for (int ni = 0; ni < 4; ni++)
                LDSM4(bh[ni], sb + bbase + (uint32_t)(bR + ni * 16) * LDAB + kOff + bC);
            #pragma unroll
            for (int mi = 0; mi < 2; mi++)
                #pragma unroll
                for (int ni = 0; ni < 4; ni++)
                    #pragma unroll
                    for (int h = 0; h < 2; h++)
                        MMA16816(acc[mi][ni * 2 + h], ah[mi], bh[ni][h * 2], bh[ni][h * 2 + 1]);
        }

        if (ct != rt) {
            // off-diagonal: row sums (registers) + column sums (smem reduce -> one atomic)
            float cs[8][2];
            #pragma unroll
            for (int nt = 0; nt < 8; nt++) { cs[nt][0] = 0.f; cs[nt][1] = 0.f; }
            #pragma unroll
            for (int mi = 0; mi < 2; mi++)
                #pragma unroll
                for (int nt = 0; nt < 8; nt++) {
                    float e0 = ex2f(acc[mi][nt][0]);
                    float e1 = ex2f(acc[mi][nt][1]);
                    float e2 = ex2f(acc[mi][nt][2]);
                    float e3 = ex2f(acc[mi][nt][3]);
                    rsum[mi][0] += e0 + e1;
                    rsum[mi][1] += e2 + e3;
                    cs[nt][0] += e0 + e2;
                    cs[nt][1] += e1 + e3;
                }
            #pragma unroll
            for (int nt = 0; nt < 8; nt++)
                #pragma unroll
                for (int sc = 0; sc < 2; sc++) {
                    float s = cs[nt][sc];
                    s += __shfl_xor_sync(0xffffffffu, s, 4);
                    s += __shfl_xor_sync(0xffffffffu, s, 8);
                    s += __shfl_xor_sync(0xffffffffu, s, 16);
                    if (g == 0) colRed[(bRow + nt * 8 + t4 * 2 + sc) * 4 + wy] = s;
                }
            __syncthreads();
            if (tid < 128)
                atomicAdd(&g_rowTot[ct * TT + tid],
                          (colRed[tid * 4] + colRed[tid * 4 + 1]) +
                          (colRed[tid * 4 + 2] + colRed[tid * 4 + 3]));
        } else {
            // diagonal tile: mask the diagonal; no column sums
            #pragma unroll
            for (int mi = 0; mi < 2; mi++) {
                const int row0 = aRow + mi * 16 + g;
                const int row1 = row0 + 8;
                #pragma unroll
                for (int nt = 0; nt < 8; nt++) {
                    const int gc = bRow + nt * 8 + t4 * 2;
                    float e0 = (row0 == gc    ) ? 0.f : ex2f(acc[mi][nt][0]);
                    float e1 = (row0 == gc + 1) ? 0.f : ex2f(acc[mi][nt][1]);
                    float e2 = (row1 == gc    ) ? 0.f : ex2f(acc[mi][nt][2]);
                    float e3 = (row1 == gc + 1) ? 0.f : ex2f(acc[mi][nt][3]);
                    rsum[mi][0] += e0 + e1;
                    rsum[mi][1] += e2 + e3;
                }
            }
        }
        if (pre) CPA_WAIT0();
        __syncthreads();   // B buffer consumed; colRed reads done
    }

    // pair-accumulated row sums -> atomic add into rowTot
    #pragma unroll
    for (int mi = 0; mi < 2; mi++)
        #pragma unroll
        for (int hrow = 0; hrow < 2; hrow++) {
            float s = rsum[mi][hrow];
            s += __shfl_xor_sync(0xffffffffu, s, 1);
            s += __shfl_xor_sync(0xffffffffu, s, 2);
            if (t4 == 0) red[(aRow + mi * 16 + hrow * 8 + g) * 2 + wx] = s;
        }
    __syncthreads();
    if (tid < 128)
        atomicAdd(&g_rowTot[rowBase + tid], red[tid * 2] + red[tid * 2 + 1]);
}

// ---------------- 5) per-class loss: 1 block/class, 512 threads, 16-warp Gram ----------------
#define CLS_SMEM (128 * LDAB + 128 * SSTR * 4)    // 34816 + 67584 = 102400
__global__ void __launch_bounds__(512, 1) class_loss_kernel(float* __restrict__ out) {
    extern __shared__ char cs_[];
    char*  tile = cs_;
    float* S    = (float*)(cs_ + 128 * LDAB);     // [128][SSTR]
    __shared__ int   gidx[CAP];
    __shared__ float unsimS[CAP];
    __shared__ float tr[512];
    __shared__ float tp[512];
    __shared__ int   isLast;
    const uint32_t sb = smem_u32(tile);
    const int c = blockIdx.x, tid = threadIdx.x, wid = tid >> 5, lane = tid & 31;
    const int base = g_ofs[c];
    int n = g_ofs[c + 1] - base;
    if (n > CAP) n = CAP;

    for (int i = tid; i < CAP; i += 512) gidx[i] = (i < n) ? g_order[base + i] : 0;
    __syncthreads();
    for (int i = tid; i < 128 * 16; i += 512) {
        int r = i >> 4, c8 = i & 15;
        uint32_t off = (uint32_t)r * LDAB + (uint32_t)c8 * 16;
        uint4 v = make_uint4(0u, 0u, 0u, 0u);
        if (r < n) v = ((const uint4*)(g_yhi + (size_t)gidx[r] * D))[c8];
        *(uint4*)(tile + off) = v;
    }
    __syncthreads();

    // full mini-Gram: 16 warps, 4(M) x 4(N); warp tile 32x32
    const int wy = wid & 3, wx = wid >> 2;
    const int aRow = wy * 32, bRow = wx * 32;
    const int aR  = aRow + (lane & 15);
    const int aC  = (lane >> 4) * 16;
    const int bR  = bRow + (lane & 7) + ((lane >> 4) << 3);
    const int bC  = ((lane >> 3) & 1) * 16;

    float acc[2][4][4];
    #pragma unroll
    for (int mi = 0; mi < 2; mi++)
        #pragma unroll
        for (int nt = 0; nt < 4; nt++)
            #pragma unroll
            for (int q = 0; q < 4; q++) acc[mi][nt][q] = 0.f;

    #pragma unroll
    for (int kk = 0; kk < 8; kk++) {
        const uint32_t kOff = (uint32_t)kk * 32;
        uint32_t ah[2][4], bh[2][4];
        #pragma unroll
        for (int mi = 0; mi < 2; mi++)
            LDSM4(ah[mi], sb + (uint32_t)(aR + mi * 16) * LDAB + kOff + aC);
        #pragma unroll
        for (int ni = 0; ni < 2; ni++)
            LDSM4(bh[ni], sb + (uint32_t)(bR + ni * 16) * LDAB + kOff + bC);
        #pragma unroll
        for (int mi = 0; mi < 2; mi++)
            #pragma unroll
            for (int ni = 0; ni < 2; ni++)
                #pragma unroll
                for (int h = 0; h < 2; h++)
                    MMA16816(acc[mi][ni * 2 + h], ah[mi], bh[ni][h * 2], bh[ni][h * 2 + 1]);
    }

    // store S — s = log2-domain sim/T
    const int g = lane >> 2, t4 = lane & 3;
    #pragma unroll
    for (int mi = 0; mi < 2; mi++) {
        const int r0 = aRow + mi * 16 + g;
        #pragma unroll
        for (int nt = 0; nt < 4; nt++) {
            const int col = bRow + nt * 8 + t4 * 2;
            *(float2*)&S[r0 * SSTR + col]       = make_float2(acc[mi][nt][0], acc[mi][nt][1]);
            *(float2*)&S[(r0 + 8) * SSTR + col] = make_float2(acc[mi][nt][2], acc[mi][nt][3]);
        }
    }
    __syncthreads();

    // possum_i -> unsim_i (16 warps over rows)
    for (int i = wid; i < n; i += 16) {
        float ps = 0.f;
        for (int j = lane; j < n; j += 32)
            if (j != i) ps += ex2f(S[i * SSTR + j]);
        #pragma unroll
        for (int o = 16; o > 0; o >>= 1) ps += __shfl_xor_sync(0xffffffffu, ps, o);
        if (lane == 0) unsimS[i] = g_rowTot[gidx[i]] - ps;
    }
    __syncthreads();

    // loss terms
    float la = 0.f;
    const int nn = n * n;
    for (int p = tid; p < nn; p += 512) {
        int i = p / n, j = p - i * n;
        if (i == j) continue;
        float s = S[i * SSTR + j];
        la += lg2f(ex2f(s) + unsimS[i]) - s;
    }
    tr[tid] = la * LN2F;
    __syncthreads();
    #pragma unroll
    for (int o = 256; o > 0; o >>= 1) {
        if (tid < o) tr[tid] += tr[tid + o];
        __syncthreads();
    }
    if (tid == 0) {
        g_classLoss[c] = tr[0];
        __threadfence();
        isLast = (atomicAdd(&g_done, 1) == NCLS - 1);
    }
    __syncthreads();
    if (isLast) {
        __threadfence();
        // parallel finalize: 128 threads load per-class results, tree-reduce
        float L = 0.f, P = 0.f;
        if (tid < NCLS) {
            L = g_classLoss[tid];
            float nc = (float)(g_ofs[tid + 1] - g_ofs[tid]);
            P = nc * (nc - 1.f);
        }
        tr[tid] = L;
        tp[tid] = P;
        __syncthreads();
        #pragma unroll
        for (int o = 64; o > 0; o >>= 1) {
            if (tid < o) { tr[tid] += tr[tid + o]; tp[tid] += tp[tid + o]; }
            __syncthreads();
        }
        if (tid == 0) {
            out[0] = tr[0] / tp[0];
            g_done = 0;   // reset for next graph replay
        }
    }
}

// ---------------- launch ----------------
extern "C" void kernel_launch(void* const* d_in, const int* in_sizes, int n_in,
                              void* d_out, int out_size) {
    const float* x     = (const float*)d_in[0];
    const int*   label = (const int*)d_in[1];
    float*       out   = (float*)d_out;

    cudaFuncSetAttribute(gram_hmma, cudaFuncAttributeMaxDynamicSharedMemorySize, SM_TOTAL);
    cudaFuncSetAttribute(class_loss_kernel, cudaFuncAttributeMaxDynamicSharedMemorySize, CLS_SMEM);

    prep_kernel<<<N / 8, 256>>>(x);
    build_ofs_kernel<<<1, 256>>>(label);
    scatter_kernel<<<NCHUNK, 256>>>(label);
    gram_hmma<<<NBLK, 256, SM_TOTAL>>>();
    class_loss_kernel<<<NCLS, 512, CLS_SMEM>>>(out);
}

// round 13
// speedup vs baseline: 1.3719x; 1.1231x over previous
#include <cuda_runtime.h>
#include <cuda_bf16.h>
#include <math.h>
#include <stdint.h>

#define N      8192
#define D      128
#define NCLS   128
#define TT     128           // gram tile (rows == cols)
#define NT     (N / TT)      // 64 tiles per dim
#define NBLK   1056          // sum over rt of ceil((64-rt)/2)
#define CAP    128           // max class size supported
#define LDAB   272           // bytes per smem tile row: 128 bf16 + 8 pad
#define SSTR   132           // S matrix row stride (floats)
#define LN2F   0.6931471805599453f

// ---------------- scratch (device globals; no allocations) ----------------
__device__ __nv_bfloat16  g_yhi[N * D];        // bf16(x * invn * sqrt(log2e/T))
__device__ float          g_rowTot[N];         // accumulated via atomicAdd (zeroed in prep)
__device__ float          g_classLoss[NCLS];
__device__ float          g_classN[NCLS];
__device__ int            g_done;              // class_loss last-block counter

// ---------------- helpers ----------------
__device__ __forceinline__ uint32_t smem_u32(const void* p) {
    uint32_t a;
    asm("{ .reg .u64 t; cvta.to.shared.u64 t, %1; cvt.u32.u64 %0, t; }" : "=r"(a) : "l"(p));
    return a;
}
__device__ __forceinline__ float ex2f(float x) {
    float r;
    asm("ex2.approx.ftz.f32 %0, %1;" : "=f"(r) : "f"(x));
    return r;
}
__device__ __forceinline__ float lg2f(float x) {
    float r;
    asm("lg2.approx.f32 %0, %1;" : "=f"(r) : "f"(x));
    return r;
}
__device__ __forceinline__ void cpa16(uint32_t dst, const void* src) {
    asm volatile("{ .reg .u64 g; cvta.to.global.u64 g, %1; cp.async.cg.shared.global [%0], [g], 16; }"
                 :: "r"(dst), "l"(src) : "memory");
}
#define CPA_COMMIT()  asm volatile("cp.async.commit_group;" ::: "memory")
#define CPA_WAIT0()   asm volatile("cp.async.wait_group 0;" ::: "memory")

#define LDSM4(r, addr)                                                           \
    asm volatile("ldmatrix.sync.aligned.m8n8.x4.shared.b16 {%0,%1,%2,%3}, [%4];" \
        : "=r"((r)[0]), "=r"((r)[1]), "=r"((r)[2]), "=r"((r)[3]) : "r"(addr))

#define MMA16816(d, a, b0r, b1r)                                                 \
    asm volatile("mma.sync.aligned.m16n8k16.row.col.f32.bf16.bf16.f32 "          \
        "{%0,%1,%2,%3}, {%4,%5,%6,%7}, {%8,%9}, {%0,%1,%2,%3};"                  \
        : "+f"((d)[0]), "+f"((d)[1]), "+f"((d)[2]), "+f"((d)[3])                 \
        : "r"((a)[0]), "r"((a)[1]), "r"((a)[2]), "r"((a)[3]), "r"(b0r), "r"(b1r))

// ---------------- 1) fused norms + prescale + bf16 + rowTot zero ----------------
__global__ void prep_kernel(const float* __restrict__ x) {
    int row  = blockIdx.x * 8 + (threadIdx.x >> 5);
    int lane = threadIdx.x & 31;
    float4 v = *(const float4*)(x + (size_t)row * D + lane * 4);
    float ss = v.x * v.x + v.y * v.y + v.z * v.z + v.w * v.w;
    #pragma unroll
    for (int o = 16; o > 0; o >>= 1) ss += __shfl_xor_sync(0xffffffffu, ss, o);
    float s = rsqrtf(fmaxf(ss, 1e-12f)) * 2.6858190963521055f;  // invn*sqrt(log2e/T)
    __nv_bfloat162 p0(__float2bfloat16(v.x * s), __float2bfloat16(v.y * s));
    __nv_bfloat162 p1(__float2bfloat16(v.z * s), __float2bfloat16(v.w * s));
    uint2 pk;
    pk.x = *(uint32_t*)&p0;
    pk.y = *(uint32_t*)&p1;
    *(uint2*)(g_yhi + (size_t)row * D + lane * 4) = pk;
    if (lane == 0) g_rowTot[row] = 0.f;   // stream-ordered before gram's atomics
}

// ---------------- 2) HMMA Gram: tile pairs, smem-reduced + atomic rowTot ----------------
#define SM_A     0
#define SM_B0    34816
#define SM_B1    69632
#define SM_RED   104448                 // red 1KB + colRed 2KB
#define SM_TOTAL (SM_RED + 3072)        // 107520 B -> 2 CTAs/SM

__device__ __forceinline__ void stage_tile(uint32_t dstBase, int rowStart, int tid) {
    for (int i = tid; i < 128 * 16; i += 256) {
        int r = i >> 4, c8 = i & 15;
        cpa16(dstBase + (uint32_t)r * LDAB + (uint32_t)c8 * 16,
              g_yhi + (size_t)(rowStart + r) * D + c8 * 8);
    }
}

__global__ void __launch_bounds__(256, 2) gram_hmma() {
    extern __shared__ char smem[];
    const uint32_t sb = smem_u32(smem);
    const int tid = threadIdx.x, wid = tid >> 5, lane = tid & 31;

    // decode block -> (rt strip, pair of column tiles starting at ct0)
    int b = blockIdx.x, rt = 0;
    for (;;) { int nc = (NT - rt + 1) >> 1; if (b < nc) break; b -= nc; rt++; }
    const int ct0 = rt + b * 2;
    const int ctEnd = (ct0 + 2 < NT) ? (ct0 + 2) : NT;
    const int rowBase = rt * TT;

    stage_tile(sb + SM_A, rowBase, tid);
    if (ct0 != rt) stage_tile(sb + SM_B0, ct0 * TT, tid);
    CPA_COMMIT();
    CPA_WAIT0();
    __syncthreads();

    const int wy = wid & 3, wx = wid >> 2;      // warp grid 4(M) x 2(N)
    const int aRow = wy * 32, bRow = wx * 64;
    const int aR  = aRow + (lane & 15);
    const int aC  = (lane >> 4) * 16;
    const int bR  = bRow + (lane & 7) + ((lane >> 4) << 3);
    const int bC  = ((lane >> 3) & 1) * 16;
    const int g = lane >> 2, t4 = lane & 3;

    float* red    = (float*)(smem + SM_RED);          // [128][2 wx]
    float* colRed = (float*)(smem + SM_RED + 1024);   // [128][4 wy]

    float rsum[2][2] = {{0.f, 0.f}, {0.f, 0.f}};      // accumulates across the pair

    for (int ct = ct0; ct < ctEnd; ct++) {
        const uint32_t bbase = (ct == rt) ? SM_A : (((ct - ct0) & 1) ? SM_B1 : SM_B0);
        const bool pre = (ct + 1 < ctEnd);
        if (pre) {   // prefetch next B while computing this tile
            stage_tile(sb + (((ct + 1 - ct0) & 1) ? SM_B1 : SM_B0), (ct + 1) * TT, tid);
            CPA_COMMIT();
        }

        float acc[2][8][4];
        #pragma unroll
        for (int mi = 0; mi < 2; mi++)
            #pragma unroll
            for (int nt = 0; nt < 8; nt++)
                #pragma unroll
                for (int q = 0; q < 4; q++) acc[mi][nt][q] = 0.f;

        #pragma unroll
        for (int kk = 0; kk < 8; kk++) {
            const uint32_t kOff = (uint32_t)kk * 32;
            uint32_t ah[2][4], bh[4][4];
            #pragma unroll
            for (int mi = 0; mi < 2; mi++)
                LDSM4(ah[mi], sb + SM_A + (uint32_t)(aR + mi * 16) * LDAB + kOff + aC);
            #pragma unroll
            for (int ni = 0; ni < 4; ni++)
                LDSM4(bh[ni], sb + bbase + (uint32_t)(bR + ni * 16) * LDAB + kOff + bC);
            #pragma unroll
            for (int mi = 0; mi < 2; mi++)
                #pragma unroll
                for (int ni = 0; ni < 4; ni++)
                    #pragma unroll
                    for (int h = 0; h < 2; h++)
                        MMA16816(acc[mi][ni * 2 + h], ah[mi], bh[ni][h * 2], bh[ni][h * 2 + 1]);
        }

        if (ct != rt) {
            // off-diagonal: row sums (registers) + column sums (smem reduce -> one atomic)
            float cs[8][2];
            #pragma unroll
            for (int nt = 0; nt < 8; nt++) { cs[nt][0] = 0.f; cs[nt][1] = 0.f; }
            #pragma unroll
            for (int mi = 0; mi < 2; mi++)
                #pragma unroll
                for (int nt = 0; nt < 8; nt++) {
                    float e0 = ex2f(acc[mi][nt][0]);
                    float e1 = ex2f(acc[mi][nt][1]);
                    float e2 = ex2f(acc[mi][nt][2]);
                    float e3 = ex2f(acc[mi][nt][3]);
                    rsum[mi][0] += e0 + e1;
                    rsum[mi][1] += e2 + e3;
                    cs[nt][0] += e0 + e2;
                    cs[nt][1] += e1 + e3;
                }
            #pragma unroll
            for (int nt = 0; nt < 8; nt++)
                #pragma unroll
                for (int sc = 0; sc < 2; sc++) {
                    float s = cs[nt][sc];
                    s += __shfl_xor_sync(0xffffffffu, s, 4);
                    s += __shfl_xor_sync(0xffffffffu, s, 8);
                    s += __shfl_xor_sync(0xffffffffu, s, 16);
                    if (g == 0) colRed[(bRow + nt * 8 + t4 * 2 + sc) * 4 + wy] = s;
                }
            __syncthreads();
            if (tid < 128)
                atomicAdd(&g_rowTot[ct * TT + tid],
                          (colRed[tid * 4] + colRed[tid * 4 + 1]) +
                          (colRed[tid * 4 + 2] + colRed[tid * 4 + 3]));
        } else {
            // diagonal tile: mask the diagonal; no column sums
            #pragma unroll
            for (int mi = 0; mi < 2; mi++) {
                const int row0 = aRow + mi * 16 + g;
                const int row1 = row0 + 8;
                #pragma unroll
                for (int nt = 0; nt < 8; nt++) {
                    const int gc = bRow + nt * 8 + t4 * 2;
                    float e0 = (row0 == gc    ) ? 0.f : ex2f(acc[mi][nt][0]);
                    float e1 = (row0 == gc + 1) ? 0.f : ex2f(acc[mi][nt][1]);
                    float e2 = (row1 == gc    ) ? 0.f : ex2f(acc[mi][nt][2]);
                    float e3 = (row1 == gc + 1) ? 0.f : ex2f(acc[mi][nt][3]);
                    rsum[mi][0] += e0 + e1;
                    rsum[mi][1] += e2 + e3;
                }
            }
        }
        if (pre) CPA_WAIT0();
        __syncthreads();   // B buffer consumed; colRed reads done
    }

    // pair-accumulated row sums -> atomic add into rowTot
    #pragma unroll
    for (int mi = 0; mi < 2; mi++)
        #pragma unroll
        for (int hrow = 0; hrow < 2; hrow++) {
            float s = rsum[mi][hrow];
            s += __shfl_xor_sync(0xffffffffu, s, 1);
            s += __shfl_xor_sync(0xffffffffu, s, 2);
            if (t4 == 0) red[(aRow + mi * 16 + hrow * 8 + g) * 2 + wx] = s;
        }
    __syncthreads();
    if (tid < 128)
        atomicAdd(&g_rowTot[rowBase + tid], red[tid * 2] + red[tid * 2 + 1]);
}

// ---------------- 3) per-class loss: in-block bucketing + 16-warp Gram + finalize ----------------
#define CLS_SMEM (128 * LDAB + 128 * SSTR * 4)    // 34816 + 67584 = 102400
__global__ void __launch_bounds__(512, 1) class_loss_kernel(const int* __restrict__ label,
                                                            float* __restrict__ out) {
    extern __shared__ char cs_[];
    char*  tile = cs_;
    float* S    = (float*)(cs_ + 128 * LDAB);     // [128][SSTR]
    __shared__ int   gidx[CAP];
    __shared__ float unsimS[CAP];
    __shared__ float tr[512];
    __shared__ float tp[512];
    __shared__ int   wS[16];
    __shared__ int   shN;
    __shared__ int   isLast;
    const uint32_t sb = smem_u32(tile);
    const int c = blockIdx.x, tid = threadIdx.x, wid = tid >> 5, lane = tid & 31;

    // --- in-block bucketing: thread t owns labels [16t, 16t+16), stable order ---
    int lab[16];
    {
        const int4* lp = (const int4*)label + tid * 4;
        int4 L0 = lp[0], L1 = lp[1], L2 = lp[2], L3 = lp[3];
        lab[0]=L0.x; lab[1]=L0.y; lab[2]=L0.z; lab[3]=L0.w;
        lab[4]=L1.x; lab[5]=L1.y; lab[6]=L1.z; lab[7]=L1.w;
        lab[8]=L2.x; lab[9]=L2.y; lab[10]=L2.z; lab[11]=L2.w;
        lab[12]=L3.x; lab[13]=L3.y; lab[14]=L3.z; lab[15]=L3.w;
    }
    int myCnt = 0;
    #pragma unroll
    for (int k = 0; k < 16; k++) myCnt += (lab[k] == c);
    // block exclusive scan: warp inclusive shfl-scan + serial 16-warp fixup
    int inc = myCnt;
    #pragma unroll
    for (int o = 1; o < 32; o <<= 1) {
        int u = __shfl_up_sync(0xffffffffu, inc, o);
        if (lane >= o) inc += u;
    }
    if (lane == 31) wS[wid] = inc;
    __syncthreads();
    if (tid == 0) {
        int run = 0;
        #pragma unroll
        for (int k = 0; k < 16; k++) { int v = wS[k]; wS[k] = run; run += v; }
        shN = (run < CAP) ? run : CAP;
    }
    __syncthreads();
    {
        int o = wS[wid] + inc - myCnt;
        #pragma unroll
        for (int k = 0; k < 16; k++)
            if (lab[k] == c) { if (o < CAP) gidx[o] = tid * 16 + k; o++; }
    }
    __syncthreads();
    const int n = shN;

    // --- stage class rows (bf16), zero-pad beyond n ---
    for (int i = tid; i < 128 * 16; i += 512) {
        int r = i >> 4, c8 = i & 15;
        uint32_t off = (uint32_t)r * LDAB + (uint32_t)c8 * 16;
        uint4 v = make_uint4(0u, 0u, 0u, 0u);
        if (r < n) v = ((const uint4*)(g_yhi + (size_t)gidx[r] * D))[c8];
        *(uint4*)(tile + off) = v;
    }
    __syncthreads();

    // --- full mini-Gram: 16 warps, 4(M) x 4(N); warp tile 32x32 ---
    const int wy = wid & 3, wx = wid >> 2;
    const int aRow = wy * 32, bRow = wx * 32;
    const int aR  = aRow + (lane & 15);
    const int aC  = (lane >> 4) * 16;
    const int bR  = bRow + (lane & 7) + ((lane >> 4) << 3);
    const int bC  = ((lane >> 3) & 1) * 16;

    float acc[2][4][4];
    #pragma unroll
    for (int mi = 0; mi < 2; mi++)
        #pragma unroll
        for (int nt = 0; nt < 4; nt++)
            #pragma unroll
            for (int q = 0; q < 4; q++) acc[mi][nt][q] = 0.f;

    #pragma unroll
    for (int kk = 0; kk < 8; kk++) {
        const uint32_t kOff = (uint32_t)kk * 32;
        uint32_t ah[2][4], bh[2][4];
        #pragma unroll
        for (int mi = 0; mi < 2; mi++)
            LDSM4(ah[mi], sb + (uint32_t)(aR + mi * 16) * LDAB + kOff + aC);
        #pragma unroll
        for (int ni = 0; ni < 2; ni++)
            LDSM4(bh[ni], sb + (uint32_t)(bR + ni * 16) * LDAB + kOff + bC);
        #pragma unroll
        for (int mi = 0; mi < 2; mi++)
            #pragma unroll
            for (int ni = 0; ni < 2; ni++)
                #pragma unroll
                for (int h = 0; h < 2; h++)
                    MMA16816(acc[mi][ni * 2 + h], ah[mi], bh[ni][h * 2], bh[ni][h * 2 + 1]);
    }

    // --- store S (log2-domain sim/T) ---
    const int g = lane >> 2, t4 = lane & 3;
    #pragma unroll
    for (int mi = 0; mi < 2; mi++) {
        const int r0 = aRow + mi * 16 + g;
        #pragma unroll
        for (int nt = 0; nt < 4; nt++) {
            const int col = bRow + nt * 8 + t4 * 2;
            *(float2*)&S[r0 * SSTR + col]       = make_float2(acc[mi][nt][0], acc[mi][nt][1]);
            *(float2*)&S[(r0 + 8) * SSTR + col] = make_float2(acc[mi][nt][2], acc[mi][nt][3]);
        }
    }
    __syncthreads();

    // --- possum_i -> unsim_i ---
    for (int i = wid; i < n; i += 16) {
        float ps = 0.f;
        for (int j = lane; j < n; j += 32)
            if (j != i) ps += ex2f(S[i * SSTR + j]);
        #pragma unroll
        for (int o = 16; o > 0; o >>= 1) ps += __shfl_xor_sync(0xffffffffu, ps, o);
        if (lane == 0) unsimS[i] = g_rowTot[gidx[i]] - ps;
    }
    __syncthreads();

    // --- loss terms ---
    float la = 0.f;
    const int nn = n * n;
    for (int p = tid; p < nn; p += 512) {
        int i = p / n, j = p - i * n;
        if (i == j) continue;
        float s = S[i * SSTR + j];
        la += lg2f(ex2f(s) + unsimS[i]) - s;
    }
    tr[tid] = la * LN2F;
    __syncthreads();
    #pragma unroll
    for (int o = 256; o > 0; o >>= 1) {
        if (tid < o) tr[tid] += tr[tid + o];
        __syncthreads();
    }
    if (tid == 0) {
        g_classLoss[c] = tr[0];
        g_classN[c] = (float)n * (float)(n - 1);
        __threadfence();
        isLast = (atomicAdd(&g_done, 1) == NCLS - 1);
    }
    __syncthreads();
    if (isLast) {
        __threadfence();
        float L = 0.f, P = 0.f;
        if (tid < NCLS) { L = g_classLoss[tid]; P = g_classN[tid]; }
        tr[tid] = L;
        tp[tid] = P;
        __syncthreads();
        #pragma unroll
        for (int o = 64; o > 0; o >>= 1) {
            if (tid < o) { tr[tid] += tr[tid + o]; tp[tid] += tp[tid + o]; }
            __syncthreads();
        }
        if (tid == 0) {
            out[0] = tr[0] / tp[0];
            g_done = 0;   // reset for next graph replay
        }
    }
}

// ---------------- launch ----------------
extern "C" void kernel_launch(void* const* d_in, const int* in_sizes, int n_in,
                              void* d_out, int out_size) {
    const float* x     = (const float*)d_in[0];
    const int*   label = (const int*)d_in[1];
    float*       out   = (float*)d_out;

    cudaFuncSetAttribute(gram_hmma, cudaFuncAttributeMaxDynamicSharedMemorySize, SM_TOTAL);
    cudaFuncSetAttribute(class_loss_kernel, cudaFuncAttributeMaxDynamicSharedMemorySize, CLS_SMEM);

    prep_kernel<<<N / 8, 256>>>(x);
    gram_hmma<<<NBLK, 256, SM_TOTAL>>>();
    class_loss_kernel<<<NCLS, 512, CLS_SMEM>>>(label, out);
}

// round 14
// speedup vs baseline: 1.3784x; 1.0047x over previous
#include <cuda_runtime.h>
#include <cuda_bf16.h>
#include <math.h>
#include <stdint.h>

#define N      8192
#define D      128
#define NCLS   128
#define TT     128           // gram tile (rows == cols)
#define NT     (N / TT)      // 64 tiles per dim
#define NBLK   1056          // sum over rt of ceil((64-rt)/2)
#define CAP    128           // max class size supported
#define LDAB   272           // bytes per smem tile row: 128 bf16 + 8 pad
#define SSTR   132           // S matrix row stride (floats)
#define LN2F   0.6931471805599453f

// ---------------- scratch (device globals; no allocations) ----------------
__device__ __nv_bfloat16  g_yhi[N * D];        // bf16(x * invn * sqrt(log2e/T))
__device__ float          g_rowTot[N];         // accumulated via atomicAdd (zeroed in prep)
__device__ float          g_classLoss[NCLS];
__device__ float          g_classN[NCLS];
__device__ int            g_done;              // class_loss last-block counter

// ---------------- helpers ----------------
__device__ __forceinline__ uint32_t smem_u32(const void* p) {
    uint32_t a;
    asm("{ .reg .u64 t; cvta.to.shared.u64 t, %1; cvt.u32.u64 %0, t; }" : "=r"(a) : "l"(p));
    return a;
}
__device__ __forceinline__ float ex2f(float x) {
    float r;
    asm("ex2.approx.ftz.f32 %0, %1;" : "=f"(r) : "f"(x));
    return r;
}
__device__ __forceinline__ float lg2f(float x) {
    float r;
    asm("lg2.approx.f32 %0, %1;" : "=f"(r) : "f"(x));
    return r;
}
__device__ __forceinline__ void cpa16(uint32_t dst, const void* src) {
    asm volatile("{ .reg .u64 g; cvta.to.global.u64 g, %1; cp.async.cg.shared.global [%0], [g], 16; }"
                 :: "r"(dst), "l"(src) : "memory");
}
#define CPA_COMMIT()  asm volatile("cp.async.commit_group;" ::: "memory")
#define CPA_WAIT0()   asm volatile("cp.async.wait_group 0;" ::: "memory")

#define LDSM4(r, addr)                                                           \
    asm volatile("ldmatrix.sync.aligned.m8n8.x4.shared.b16 {%0,%1,%2,%3}, [%4];" \
        : "=r"((r)[0]), "=r"((r)[1]), "=r"((r)[2]), "=r"((r)[3]) : "r"(addr))

#define MMA16816(d, a, b0r, b1r)                                                 \
    asm volatile("mma.sync.aligned.m16n8k16.row.col.f32.bf16.bf16.f32 "          \
        "{%0,%1,%2,%3}, {%4,%5,%6,%7}, {%8,%9}, {%0,%1,%2,%3};"                  \
        : "+f"((d)[0]), "+f"((d)[1]), "+f"((d)[2]), "+f"((d)[3])                 \
        : "r"((a)[0]), "r"((a)[1]), "r"((a)[2]), "r"((a)[3]), "r"(b0r), "r"(b1r))

// ---------------- 1) fused norms + prescale + bf16 + rowTot zero ----------------
// grid 128 x 256: each warp owns 8 rows; all 8 loads issued upfront (MLP=8),
// then 8 independent shfl-reduce chains interleave.
__global__ void prep_kernel(const float* __restrict__ x) {
    const int warp = threadIdx.x >> 5, lane = threadIdx.x & 31;
    const int row0 = blockIdx.x * 64 + warp * 8;
    float4 v[8];
    #pragma unroll
    for (int r = 0; r < 8; r++)
        v[r] = *(const float4*)(x + (size_t)(row0 + r) * D + lane * 4);
    #pragma unroll
    for (int r = 0; r < 8; r++) {
        float ss = v[r].x * v[r].x + v[r].y * v[r].y + v[r].z * v[r].z + v[r].w * v[r].w;
        #pragma unroll
        for (int o = 16; o > 0; o >>= 1) ss += __shfl_xor_sync(0xffffffffu, ss, o);
        float s = rsqrtf(fmaxf(ss, 1e-12f)) * 2.6858190963521055f;  // invn*sqrt(log2e/T)
        __nv_bfloat162 p0(__float2bfloat16(v[r].x * s), __float2bfloat16(v[r].y * s));
        __nv_bfloat162 p1(__float2bfloat16(v[r].z * s), __float2bfloat16(v[r].w * s));
        uint2 pk;
        pk.x = *(uint32_t*)&p0;
        pk.y = *(uint32_t*)&p1;
        *(uint2*)(g_yhi + (size_t)(row0 + r) * D + lane * 4) = pk;
        if (lane == (int)(r << 2)) g_rowTot[row0 + r] = 0.f;  // spread across lanes
    }
}

// ---------------- 2) HMMA Gram: tile pairs, smem-reduced + atomic rowTot ----------------
#define SM_A     0
#define SM_B0    34816
#define SM_B1    69632
#define SM_RED   104448                 // red 1KB + colRed 2KB
#define SM_TOTAL (SM_RED + 3072)        // 107520 B -> 2 CTAs/SM

__device__ __forceinline__ void stage_tile(uint32_t dstBase, int rowStart, int tid) {
    for (int i = tid; i < 128 * 16; i += 256) {
        int r = i >> 4, c8 = i & 15;
        cpa16(dstBase + (uint32_t)r * LDAB + (uint32_t)c8 * 16,
              g_yhi + (size_t)(rowStart + r) * D + c8 * 8);
    }
}

__global__ void __launch_bounds__(256, 2) gram_hmma() {
    extern __shared__ char smem[];
    const uint32_t sb = smem_u32(smem);
    const int tid = threadIdx.x, wid = tid >> 5, lane = tid & 31;

    // decode block -> (rt strip, pair of column tiles starting at ct0)
    int b = blockIdx.x, rt = 0;
    for (;;) { int nc = (NT - rt + 1) >> 1; if (b < nc) break; b -= nc; rt++; }
    const int ct0 = rt + b * 2;
    const int ctEnd = (ct0 + 2 < NT) ? (ct0 + 2) : NT;
    const int rowBase = rt * TT;

    stage_tile(sb + SM_A, rowBase, tid);
    if (ct0 != rt) stage_tile(sb + SM_B0, ct0 * TT, tid);
    CPA_COMMIT();
    CPA_WAIT0();
    __syncthreads();

    const int wy = wid & 3, wx = wid >> 2;      // warp grid 4(M) x 2(N)
    const int aRow = wy * 32, bRow = wx * 64;
    const int aR  = aRow + (lane & 15);
    const int aC  = (lane >> 4) * 16;
    const int bR  = bRow + (lane & 7) + ((lane >> 4) << 3);
    const int bC  = ((lane >> 3) & 1) * 16;
    const int g = lane >> 2, t4 = lane & 3;

    float* red    = (float*)(smem + SM_RED);          // [128][2 wx]
    float* colRed = (float*)(smem + SM_RED + 1024);   // [128][4 wy]

    float rsum[2][2] = {{0.f, 0.f}, {0.f, 0.f}};      // accumulates across the pair

    for (int ct = ct0; ct < ctEnd; ct++) {
        const uint32_t bbase = (ct == rt) ? SM_A : (((ct - ct0) & 1) ? SM_B1 : SM_B0);
        const bool pre = (ct + 1 < ctEnd);
        if (pre) {   // prefetch next B while computing this tile
            stage_tile(sb + (((ct + 1 - ct0) & 1) ? SM_B1 : SM_B0), (ct + 1) * TT, tid);
            CPA_COMMIT();
        }

        float acc[2][8][4];
        #pragma unroll
        for (int mi = 0; mi < 2; mi++)
            #pragma unroll
            for (int nt = 0; nt < 8; nt++)
                #pragma unroll
                for (int q = 0; q < 4; q++) acc[mi][nt][q] = 0.f;

        #pragma unroll
        for (int kk = 0; kk < 8; kk++) {
            const uint32_t kOff = (uint32_t)kk * 32;
            uint32_t ah[2][4], bh[4][4];
            #pragma unroll
            for (int mi = 0; mi < 2; mi++)
                LDSM4(ah[mi], sb + SM_A + (uint32_t)(aR + mi * 16) * LDAB + kOff + aC);
            #pragma unroll
            for (int ni = 0; ni < 4; ni++)
                LDSM4(bh[ni], sb + bbase + (uint32_t)(bR + ni * 16) * LDAB + kOff + bC);
            #pragma unroll
            for (int mi = 0; mi < 2; mi++)
                #pragma unroll
                for (int ni = 0; ni < 4; ni++)
                    #pragma unroll
                    for (int h = 0; h < 2; h++)
                        MMA16816(acc[mi][ni * 2 + h], ah[mi], bh[ni][h * 2], bh[ni][h * 2 + 1]);
        }

        if (ct != rt) {
            // off-diagonal: row sums (registers) + column sums (smem reduce -> one atomic)
            float cs[8][2];
            #pragma unroll
            for (int nt = 0; nt < 8; nt++) { cs[nt][0] = 0.f; cs[nt][1] = 0.f; }
            #pragma unroll
            for (int mi = 0; mi < 2; mi++)
                #pragma unroll
                for (int nt = 0; nt < 8; nt++) {
                    float e0 = ex2f(acc[mi][nt][0]);
                    float e1 = ex2f(acc[mi][nt][1]);
                    float e2 = ex2f(acc[mi][nt][2]);
                    float e3 = ex2f(acc[mi][nt][3]);
                    rsum[mi][0] += e0 + e1;
                    rsum[mi][1] += e2 + e3;
                    cs[nt][0] += e0 + e2;
                    cs[nt][1] += e1 + e3;
                }
            #pragma unroll
            for (int nt = 0; nt < 8; nt++)
                #pragma unroll
                for (int sc = 0; sc < 2; sc++) {
                    float s = cs[nt][sc];
                    s += __shfl_xor_sync(0xffffffffu, s, 4);
                    s += __shfl_xor_sync(0xffffffffu, s, 8);
                    s += __shfl_xor_sync(0xffffffffu, s, 16);
                    if (g == 0) colRed[(bRow + nt * 8 + t4 * 2 + sc) * 4 + wy] = s;
                }
            __syncthreads();
            if (tid < 128)
                atomicAdd(&g_rowTot[ct * TT + tid],
                          (colRed[tid * 4] + colRed[tid * 4 + 1]) +
                          (colRed[tid * 4 + 2] + colRed[tid * 4 + 3]));
        } else {
            // diagonal tile: mask the diagonal; no column sums
            #pragma unroll
            for (int mi = 0; mi < 2; mi++) {
                const int row0 = aRow + mi * 16 + g;
                const int row1 = row0 + 8;
                #pragma unroll
                for (int nt = 0; nt < 8; nt++) {
                    const int gc = bRow + nt * 8 + t4 * 2;
                    float e0 = (row0 == gc    ) ? 0.f : ex2f(acc[mi][nt][0]);
                    float e1 = (row0 == gc + 1) ? 0.f : ex2f(acc[mi][nt][1]);
                    float e2 = (row1 == gc    ) ? 0.f : ex2f(acc[mi][nt][2]);
                    float e3 = (row1 == gc + 1) ? 0.f : ex2f(acc[mi][nt][3]);
                    rsum[mi][0] += e0 + e1;
                    rsum[mi][1] += e2 + e3;
                }
            }
        }
        if (pre) CPA_WAIT0();
        __syncthreads();   // B buffer consumed; colRed reads done
    }

    // pair-accumulated row sums -> atomic add into rowTot
    #pragma unroll
    for (int mi = 0; mi < 2; mi++)
        #pragma unroll
        for (int hrow = 0; hrow < 2; hrow++) {
            float s = rsum[mi][hrow];
            s += __shfl_xor_sync(0xffffffffu, s, 1);
            s += __shfl_xor_sync(0xffffffffu, s, 2);
            if (t4 == 0) red[(aRow + mi * 16 + hrow * 8 + g) * 2 + wx] = s;
        }
    __syncthreads();
    if (tid < 128)
        atomicAdd(&g_rowTot[rowBase + tid], red[tid * 2] + red[tid * 2 + 1]);
}

// ---------------- 3) per-class loss: in-block bucketing + guarded 16-warp Gram ----------------
#define CLS_SMEM (128 * LDAB + 128 * SSTR * 4)    // 34816 + 67584 = 102400
__global__ void __launch_bounds__(512, 1) class_loss_kernel(const int* __restrict__ label,
                                                            float* __restrict__ out) {
    extern __shared__ char cs_[];
    char*  tile = cs_;
    float* S    = (float*)(cs_ + 128 * LDAB);     // [128][SSTR]
    __shared__ int   gidx[CAP];
    __shared__ float unsimS[CAP];
    __shared__ float tr[512];
    __shared__ float tp[512];
    __shared__ int   wS[16];
    __shared__ int   shN;
    __shared__ int   isLast;
    const uint32_t sb = smem_u32(tile);
    const int c = blockIdx.x, tid = threadIdx.x, wid = tid >> 5, lane = tid & 31;

    // --- in-block bucketing: thread t owns labels [16t, 16t+16), stable order ---
    int lab[16];
    {
        const int4* lp = (const int4*)label + tid * 4;
        int4 L0 = lp[0], L1 = lp[1], L2 = lp[2], L3 = lp[3];
        lab[0]=L0.x; lab[1]=L0.y; lab[2]=L0.z; lab[3]=L0.w;
        lab[4]=L1.x; lab[5]=L1.y; lab[6]=L1.z; lab[7]=L1.w;
        lab[8]=L2.x; lab[9]=L2.y; lab[10]=L2.z; lab[11]=L2.w;
        lab[12]=L3.x; lab[13]=L3.y; lab[14]=L3.z; lab[15]=L3.w;
    }
    int myCnt = 0;
    #pragma unroll
    for (int k = 0; k < 16; k++) myCnt += (lab[k] == c);
    int inc = myCnt;
    #pragma unroll
    for (int o = 1; o < 32; o <<= 1) {
        int u = __shfl_up_sync(0xffffffffu, inc, o);
        if (lane >= o) inc += u;
    }
    if (lane == 31) wS[wid] = inc;
    __syncthreads();
    if (tid == 0) {
        int run = 0;
        #pragma unroll
        for (int k = 0; k < 16; k++) { int v = wS[k]; wS[k] = run; run += v; }
        shN = (run < CAP) ? run : CAP;
    }
    __syncthreads();
    {
        int o = wS[wid] + inc - myCnt;
        #pragma unroll
        for (int k = 0; k < 16; k++)
            if (lab[k] == c) { if (o < CAP) gidx[o] = tid * 16 + k; o++; }
    }
    __syncthreads();
    const int n = shN;

    // --- stage class rows (bf16), zero-pad beyond n ---
    for (int i = tid; i < 128 * 16; i += 512) {
        int r = i >> 4, c8 = i & 15;
        uint32_t off = (uint32_t)r * LDAB + (uint32_t)c8 * 16;
        uint4 v = make_uint4(0u, 0u, 0u, 0u);
        if (r < n) v = ((const uint4*)(g_yhi + (size_t)gidx[r] * D))[c8];
        *(uint4*)(tile + off) = v;
    }
    __syncthreads();

    // --- guarded mini-Gram: 16 warps, 4(M) x 4(N); skip warps fully outside n x n ---
    const int wy = wid & 3, wx = wid >> 2;
    const int aRow = wy * 32, bRow = wx * 32;
    const int aR  = aRow + (lane & 15);
    const int aC  = (lane >> 4) * 16;
    const int bR  = bRow + (lane & 7) + ((lane >> 4) << 3);
    const int bC  = ((lane >> 3) & 1) * 16;
    const int g = lane >> 2, t4 = lane & 3;

    if (aRow < n && bRow < n) {
        float acc[2][4][4];
        #pragma unroll
        for (int mi = 0; mi < 2; mi++)
            #pragma unroll
            for (int nt = 0; nt < 4; nt++)
                #pragma unroll
                for (int q = 0; q < 4; q++) acc[mi][nt][q] = 0.f;

        #pragma unroll
        for (int kk = 0; kk < 8; kk++) {
            const uint32_t kOff = (uint32_t)kk * 32;
            uint32_t ah[2][4], bh[2][4];
            #pragma unroll
            for (int mi = 0; mi < 2; mi++)
                LDSM4(ah[mi], sb + (uint32_t)(aR + mi * 16) * LDAB + kOff + aC);
            #pragma unroll
            for (int ni = 0; ni < 2; ni++)
                LDSM4(bh[ni], sb + (uint32_t)(bR + ni * 16) * LDAB + kOff + bC);
            #pragma unroll
            for (int mi = 0; mi < 2; mi++)
                #pragma unroll
                for (int ni = 0; ni < 2; ni++)
                    #pragma unroll
                    for (int h = 0; h < 2; h++)
                        MMA16816(acc[mi][ni * 2 + h], ah[mi], bh[ni][h * 2], bh[ni][h * 2 + 1]);
        }

        // store S (log2-domain sim/T)
        #pragma unroll
        for (int mi = 0; mi < 2; mi++) {
            const int r0 = aRow + mi * 16 + g;
            #pragma unroll
            for (int nt = 0; nt < 4; nt++) {
                const int col = bRow + nt * 8 + t4 * 2;
                *(float2*)&S[r0 * SSTR + col]       = make_float2(acc[mi][nt][0], acc[mi][nt][1]);
                *(float2*)&S[(r0 + 8) * SSTR + col] = make_float2(acc[mi][nt][2], acc[mi][nt][3]);
            }
        }
    }
    __syncthreads();

    // --- possum_i -> unsim_i ---
    for (int i = wid; i < n; i += 16) {
        float ps = 0.f;
        for (int j = lane; j < n; j += 32)
            if (j != i) ps += ex2f(S[i * SSTR + j]);
        #pragma unroll
        for (int o = 16; o > 0; o >>= 1) ps += __shfl_xor_sync(0xffffffffu, ps, o);
        if (lane == 0) unsimS[i] = g_rowTot[gidx[i]] - ps;
    }
    __syncthreads();

    // --- loss terms ---
    float la = 0.f;
    const int nn = n * n;
    for (int p = tid; p < nn; p += 512) {
        int i = p / n, j = p - i * n;
        if (i == j) continue;
        float s = S[i * SSTR + j];
        la += lg2f(ex2f(s) + unsimS[i]) - s;
    }
    tr[tid] = la * LN2F;
    __syncthreads();
    #pragma unroll
    for (int o = 256; o > 0; o >>= 1) {
        if (tid < o) tr[tid] += tr[tid + o];
        __syncthreads();
    }
    if (tid == 0) {
        g_classLoss[c] = tr[0];
        g_classN[c] = (float)n * (float)(n - 1);
        __threadfence();
        isLast = (atomicAdd(&g_done, 1) == NCLS - 1);
    }
    __syncthreads();
    if (isLast) {
        __threadfence();
        float L = 0.f, P = 0.f;
        if (tid < NCLS) { L = g_classLoss[tid]; P = g_classN[tid]; }
        tr[tid] = L;
        tp[tid] = P;
        __syncthreads();
        #pragma unroll
        for (int o = 64; o > 0; o >>= 1) {
            if (tid < o) { tr[tid] += tr[tid + o]; tp[tid] += tp[tid + o]; }
            __syncthreads();
        }
        if (tid == 0) {
            out[0] = tr[0] / tp[0];
            g_done = 0;   // reset for next graph replay
        }
    }
}

// ---------------- launch ----------------
extern "C" void kernel_launch(void* const* d_in, const int* in_sizes, int n_in,
                              void* d_out, int out_size) {
    const float* x     = (const float*)d_in[0];
    const int*   label = (const int*)d_in[1];
    float*       out   = (float*)d_out;

    cudaFuncSetAttribute(gram_hmma, cudaFuncAttributeMaxDynamicSharedMemorySize, SM_TOTAL);
    cudaFuncSetAttribute(class_loss_kernel, cudaFuncAttributeMaxDynamicSharedMemorySize, CLS_SMEM);

    prep_kernel<<<N / 64, 256>>>(x);
    gram_hmma<<<NBLK, 256, SM_TOTAL>>>();
    class_loss_kernel<<<NCLS, 512, CLS_SMEM>>>(label, out);
}

// round 15
// speedup vs baseline: 1.3915x; 1.0095x over previous
#include <cuda_runtime.h>
#include <cuda_bf16.h>
#include <math.h>
#include <stdint.h>

#define N      8192
#define D      128
#define NCLS   128
#define TT     128           // gram tile (rows == cols)
#define NT     (N / TT)      // 64 tiles per dim
#define NBLK   1056          // sum over rt of ceil((64-rt)/2)
#define CAP    128           // max class size supported
#define LDAB   272           // bytes per smem tile row: 128 bf16 + 8 pad
#define SSTR   132           // S matrix row stride (floats)
#define LN2F   0.6931471805599453f

// ---------------- scratch (device globals; no allocations) ----------------
__device__ __nv_bfloat16  g_yhi[N * D];        // bf16(x * invn * sqrt(log2e/T))
__device__ float          g_rowTot[N];         // accumulated via atomicAdd (zeroed in prep)
__device__ float          g_classLoss[NCLS];
__device__ float          g_classN[NCLS];
__device__ int            g_done;              // class_loss last-block counter

// ---------------- helpers ----------------
__device__ __forceinline__ uint32_t smem_u32(const void* p) {
    uint32_t a;
    asm("{ .reg .u64 t; cvta.to.shared.u64 t, %1; cvt.u32.u64 %0, t; }" : "=r"(a) : "l"(p));
    return a;
}
__device__ __forceinline__ float ex2f(float x) {
    float r;
    asm("ex2.approx.ftz.f32 %0, %1;" : "=f"(r) : "f"(x));
    return r;
}
__device__ __forceinline__ float lg2f(float x) {
    float r;
    asm("lg2.approx.f32 %0, %1;" : "=f"(r) : "f"(x));
    return r;
}
__device__ __forceinline__ void cpa16(uint32_t dst, const void* src) {
    asm volatile("{ .reg .u64 g; cvta.to.global.u64 g, %1; cp.async.cg.shared.global [%0], [g], 16; }"
                 :: "r"(dst), "l"(src) : "memory");
}
#define CPA_COMMIT()  asm volatile("cp.async.commit_group;" ::: "memory")
#define CPA_WAIT0()   asm volatile("cp.async.wait_group 0;" ::: "memory")

#define LDSM4(r, addr)                                                           \
    asm volatile("ldmatrix.sync.aligned.m8n8.x4.shared.b16 {%0,%1,%2,%3}, [%4];" \
        : "=r"((r)[0]), "=r"((r)[1]), "=r"((r)[2]), "=r"((r)[3]) : "r"(addr))

#define MMA16816(d, a, b0r, b1r)                                                 \
    asm volatile("mma.sync.aligned.m16n8k16.row.col.f32.bf16.bf16.f32 "          \
        "{%0,%1,%2,%3}, {%4,%5,%6,%7}, {%8,%9}, {%0,%1,%2,%3};"                  \
        : "+f"((d)[0]), "+f"((d)[1]), "+f"((d)[2]), "+f"((d)[3])                 \
        : "r"((a)[0]), "r"((a)[1]), "r"((a)[2]), "r"((a)[3]), "r"(b0r), "r"(b1r))

// ---------------- 1) fused norms + prescale + bf16 + rowTot zero ----------------
// grid 512 x 256: each warp owns 2 rows (MLP=2, only 8 data regs), high occupancy.
__global__ void __launch_bounds__(256) prep_kernel(const float* __restrict__ x) {
    const int warp = threadIdx.x >> 5, lane = threadIdx.x & 31;
    const int row0 = blockIdx.x * 16 + warp * 2;
    float4 v0 = *(const float4*)(x + (size_t)row0 * D + lane * 4);
    float4 v1 = *(const float4*)(x + (size_t)(row0 + 1) * D + lane * 4);
    float s0 = v0.x * v0.x + v0.y * v0.y + v0.z * v0.z + v0.w * v0.w;
    float s1 = v1.x * v1.x + v1.y * v1.y + v1.z * v1.z + v1.w * v1.w;
    #pragma unroll
    for (int o = 16; o > 0; o >>= 1) {
        s0 += __shfl_xor_sync(0xffffffffu, s0, o);
        s1 += __shfl_xor_sync(0xffffffffu, s1, o);
    }
    float a0 = rsqrtf(fmaxf(s0, 1e-12f)) * 2.6858190963521055f;  // invn*sqrt(log2e/T)
    float a1 = rsqrtf(fmaxf(s1, 1e-12f)) * 2.6858190963521055f;
    __nv_bfloat162 p00(__float2bfloat16(v0.x * a0), __float2bfloat16(v0.y * a0));
    __nv_bfloat162 p01(__float2bfloat16(v0.z * a0), __float2bfloat16(v0.w * a0));
    __nv_bfloat162 p10(__float2bfloat16(v1.x * a1), __float2bfloat16(v1.y * a1));
    __nv_bfloat162 p11(__float2bfloat16(v1.z * a1), __float2bfloat16(v1.w * a1));
    uint2 k0, k1;
    k0.x = *(uint32_t*)&p00; k0.y = *(uint32_t*)&p01;
    k1.x = *(uint32_t*)&p10; k1.y = *(uint32_t*)&p11;
    *(uint2*)(g_yhi + (size_t)row0 * D + lane * 4)       = k0;
    *(uint2*)(g_yhi + (size_t)(row0 + 1) * D + lane * 4) = k1;
    if (lane == 0) g_rowTot[row0] = 0.f;
    if (lane == 16) g_rowTot[row0 + 1] = 0.f;
}

// ---------------- 2) HMMA Gram: tile pairs, smem-reduced + atomic rowTot ----------------
#define SM_A     0
#define SM_B0    34816
#define SM_B1    69632
#define SM_RED   104448                 // red 1KB + colRed 2KB
#define SM_TOTAL (SM_RED + 3072)        // 107520 B -> 2 CTAs/SM

__device__ __forceinline__ void stage_tile(uint32_t dstBase, int rowStart, int tid) {
    for (int i = tid; i < 128 * 16; i += 256) {
        int r = i >> 4, c8 = i & 15;
        cpa16(dstBase + (uint32_t)r * LDAB + (uint32_t)c8 * 16,
              g_yhi + (size_t)(rowStart + r) * D + c8 * 8);
    }
}

__global__ void __launch_bounds__(256, 2) gram_hmma() {
    extern __shared__ char smem[];
    const uint32_t sb = smem_u32(smem);
    const int tid = threadIdx.x, wid = tid >> 5, lane = tid & 31;

    // decode block -> (rt strip, pair of column tiles starting at ct0)
    int b = blockIdx.x, rt = 0;
    for (;;) { int nc = (NT - rt + 1) >> 1; if (b < nc) break; b -= nc; rt++; }
    const int ct0 = rt + b * 2;
    const int ctEnd = (ct0 + 2 < NT) ? (ct0 + 2) : NT;
    const int rowBase = rt * TT;

    stage_tile(sb + SM_A, rowBase, tid);
    if (ct0 != rt) stage_tile(sb + SM_B0, ct0 * TT, tid);
    CPA_COMMIT();
    CPA_WAIT0();
    __syncthreads();

    const int wy = wid & 3, wx = wid >> 2;      // warp grid 4(M) x 2(N)
    const int aRow = wy * 32, bRow = wx * 64;
    const int aR  = aRow + (lane & 15);
    const int aC  = (lane >> 4) * 16;
    const int bR  = bRow + (lane & 7) + ((lane >> 4) << 3);
    const int bC  = ((lane >> 3) & 1) * 16;
    const int g = lane >> 2, t4 = lane & 3;

    float* red    = (float*)(smem + SM_RED);          // [128][2 wx]
    float* colRed = (float*)(smem + SM_RED + 1024);   // [128][4 wy]

    float rsum[2][2] = {{0.f, 0.f}, {0.f, 0.f}};      // accumulates across the pair

    for (int ct = ct0; ct < ctEnd; ct++) {
        const uint32_t bbase = (ct == rt) ? SM_A : (((ct - ct0) & 1) ? SM_B1 : SM_B0);
        const bool pre = (ct + 1 < ctEnd);
        if (pre) {   // prefetch next B while computing this tile
            stage_tile(sb + (((ct + 1 - ct0) & 1) ? SM_B1 : SM_B0), (ct + 1) * TT, tid);
            CPA_COMMIT();
        }

        float acc[2][8][4];
        #pragma unroll
        for (int mi = 0; mi < 2; mi++)
            #pragma unroll
            for (int nt = 0; nt < 8; nt++)
                #pragma unroll
                for (int q = 0; q < 4; q++) acc[mi][nt][q] = 0.f;

        #pragma unroll
        for (int kk = 0; kk < 8; kk++) {
            const uint32_t kOff = (uint32_t)kk * 32;
            uint32_t ah[2][4], bh[4][4];
            #pragma unroll
            for (int mi = 0; mi < 2; mi++)
                LDSM4(ah[mi], sb + SM_A + (uint32_t)(aR + mi * 16) * LDAB + kOff + aC);
            #pragma unroll
            for (int ni = 0; ni < 4; ni++)
                LDSM4(bh[ni], sb + bbase + (uint32_t)(bR + ni * 16) * LDAB + kOff + bC);
            #pragma unroll
            for (int mi = 0; mi < 2; mi++)
                #pragma unroll
                for (int ni = 0; ni < 4; ni++)
                    #pragma unroll
                    for (int h = 0; h < 2; h++)
                        MMA16816(acc[mi][ni * 2 + h], ah[mi], bh[ni][h * 2], bh[ni][h * 2 + 1]);
        }

        if (ct != rt) {
            // off-diagonal: row sums (registers) + column sums (smem reduce -> one atomic)
            float cs[8][2];
            #pragma unroll
            for (int nt = 0; nt < 8; nt++) { cs[nt][0] = 0.f; cs[nt][1] = 0.f; }
            #pragma unroll
            for (int mi = 0; mi < 2; mi++)
                #pragma unroll
                for (int nt = 0; nt < 8; nt++) {
                    float e0 = ex2f(acc[mi][nt][0]);
                    float e1 = ex2f(acc[mi][nt][1]);
                    float e2 = ex2f(acc[mi][nt][2]);
                    float e3 = ex2f(acc[mi][nt][3]);
                    rsum[mi][0] += e0 + e1;
                    rsum[mi][1] += e2 + e3;
                    cs[nt][0] += e0 + e2;
                    cs[nt][1] += e1 + e3;
                }
            #pragma unroll
            for (int nt = 0; nt < 8; nt++)
                #pragma unroll
                for (int sc = 0; sc < 2; sc++) {
                    float s = cs[nt][sc];
                    s += __shfl_xor_sync(0xffffffffu, s, 4);
                    s += __shfl_xor_sync(0xffffffffu, s, 8);
                    s += __shfl_xor_sync(0xffffffffu, s, 16);
                    if (g == 0) colRed[(bRow + nt * 8 + t4 * 2 + sc) * 4 + wy] = s;
                }
            __syncthreads();
            if (tid < 128)
                atomicAdd(&g_rowTot[ct * TT + tid],
                          (colRed[tid * 4] + colRed[tid * 4 + 1]) +
                          (colRed[tid * 4 + 2] + colRed[tid * 4 + 3]));
        } else {
            // diagonal tile: mask the diagonal; no column sums
            #pragma unroll
            for (int mi = 0; mi < 2; mi++) {
                const int row0 = aRow + mi * 16 + g;
                const int row1 = row0 + 8;
                #pragma unroll
                for (int nt = 0; nt < 8; nt++) {
                    const int gc = bRow + nt * 8 + t4 * 2;
                    float e0 = (row0 == gc    ) ? 0.f : ex2f(acc[mi][nt][0]);
                    float e1 = (row0 == gc + 1) ? 0.f : ex2f(acc[mi][nt][1]);
                    float e2 = (row1 == gc    ) ? 0.f : ex2f(acc[mi][nt][2]);
                    float e3 = (row1 == gc + 1) ? 0.f : ex2f(acc[mi][nt][3]);
                    rsum[mi][0] += e0 + e1;
                    rsum[mi][1] += e2 + e3;
                }
            }
        }
        if (pre) CPA_WAIT0();
        __syncthreads();   // B buffer consumed; colRed reads done
    }

    // pair-accumulated row sums -> atomic add into rowTot
    #pragma unroll
    for (int mi = 0; mi < 2; mi++)
        #pragma unroll
        for (int hrow = 0; hrow < 2; hrow++) {
            float s = rsum[mi][hrow];
            s += __shfl_xor_sync(0xffffffffu, s, 1);
            s += __shfl_xor_sync(0xffffffffu, s, 2);
            if (t4 == 0) red[(aRow + mi * 16 + hrow * 8 + g) * 2 + wx] = s;
        }
    __syncthreads();
    if (tid < 128)
        atomicAdd(&g_rowTot[rowBase + tid], red[tid * 2] + red[tid * 2 + 1]);
}

// ---------------- 3) per-class loss: in-block bucketing + guarded 16-warp Gram ----------------
#define CLS_SMEM (128 * LDAB + 128 * SSTR * 4)    // 34816 + 67584 = 102400
__global__ void __launch_bounds__(512, 1) class_loss_kernel(const int* __restrict__ label,
                                                            float* __restrict__ out) {
    extern __shared__ char cs_[];
    char*  tile = cs_;
    float* S    = (float*)(cs_ + 128 * LDAB);     // [128][SSTR]
    __shared__ int   gidx[CAP];
    __shared__ float unsimS[CAP];
    __shared__ float tr[512];
    __shared__ float tp[512];
    __shared__ int   wS[16];
    __shared__ int   shN;
    __shared__ int   isLast;
    const uint32_t sb = smem_u32(tile);
    const int c = blockIdx.x, tid = threadIdx.x, wid = tid >> 5, lane = tid & 31;

    // --- in-block bucketing: thread t owns labels [16t, 16t+16), stable order ---
    int lab[16];
    {
        const int4* lp = (const int4*)label + tid * 4;
        int4 L0 = lp[0], L1 = lp[1], L2 = lp[2], L3 = lp[3];
        lab[0]=L0.x; lab[1]=L0.y; lab[2]=L0.z; lab[3]=L0.w;
        lab[4]=L1.x; lab[5]=L1.y; lab[6]=L1.z; lab[7]=L1.w;
        lab[8]=L2.x; lab[9]=L2.y; lab[10]=L2.z; lab[11]=L2.w;
        lab[12]=L3.x; lab[13]=L3.y; lab[14]=L3.z; lab[15]=L3.w;
    }
    int myCnt = 0;
    #pragma unroll
    for (int k = 0; k < 16; k++) myCnt += (lab[k] == c);
    int inc = myCnt;
    #pragma unroll
    for (int o = 1; o < 32; o <<= 1) {
        int u = __shfl_up_sync(0xffffffffu, inc, o);
        if (lane >= o) inc += u;
    }
    if (lane == 31) wS[wid] = inc;
    __syncthreads();
    if (tid == 0) {
        int run = 0;
        #pragma unroll
        for (int k = 0; k < 16; k++) { int v = wS[k]; wS[k] = run; run += v; }
        shN = (run < CAP) ? run : CAP;
    }
    __syncthreads();
    {
        int o = wS[wid] + inc - myCnt;
        #pragma unroll
        for (int k = 0; k < 16; k++)
            if (lab[k] == c) { if (o < CAP) gidx[o] = tid * 16 + k; o++; }
    }
    __syncthreads();
    const int n = shN;

    // --- stage class rows (bf16), zero-pad beyond n ---
    for (int i = tid; i < 128 * 16; i += 512) {
        int r = i >> 4, c8 = i & 15;
        uint32_t off = (uint32_t)r * LDAB + (uint32_t)c8 * 16;
        uint4 v = make_uint4(0u, 0u, 0u, 0u);
        if (r < n) v = ((const uint4*)(g_yhi + (size_t)gidx[r] * D))[c8];
        *(uint4*)(tile + off) = v;
    }
    __syncthreads();

    // --- guarded mini-Gram: 16 warps, 4(M) x 4(N); skip warps fully outside n x n ---
    const int wy = wid & 3, wx = wid >> 2;
    const int aRow = wy * 32, bRow = wx * 32;
    const int aR  = aRow + (lane & 15);
    const int aC  = (lane >> 4) * 16;
    const int bR  = bRow + (lane & 7) + ((lane >> 4) << 3);
    const int bC  = ((lane >> 3) & 1) * 16;
    const int g = lane >> 2, t4 = lane & 3;

    if (aRow < n && bRow < n) {
        float acc[2][4][4];
        #pragma unroll
        for (int mi = 0; mi < 2; mi++)
            #pragma unroll
            for (int nt = 0; nt < 4; nt++)
                #pragma unroll
                for (int q = 0; q < 4; q++) acc[mi][nt][q] = 0.f;

        #pragma unroll
        for (int kk = 0; kk < 8; kk++) {
            const uint32_t kOff = (uint32_t)kk * 32;
            uint32_t ah[2][4], bh[2][4];
            #pragma unroll
            for (int mi = 0; mi < 2; mi++)
                LDSM4(ah[mi], sb + (uint32_t)(aR + mi * 16) * LDAB + kOff + aC);
            #pragma unroll
            for (int ni = 0; ni < 2; ni++)
                LDSM4(bh[ni], sb + (uint32_t)(bR + ni * 16) * LDAB + kOff + bC);
            #pragma unroll
            for (int mi = 0; mi < 2; mi++)
                #pragma unroll
                for (int ni = 0; ni < 2; ni++)
                    #pragma unroll
                    for (int h = 0; h < 2; h++)
                        MMA16816(acc[mi][ni * 2 + h], ah[mi], bh[ni][h * 2], bh[ni][h * 2 + 1]);
        }

        // store S (log2-domain sim/T)
        #pragma unroll
        for (int mi = 0; mi < 2; mi++) {
            const int r0 = aRow + mi * 16 + g;
            #pragma unroll
            for (int nt = 0; nt < 4; nt++) {
                const int col = bRow + nt * 8 + t4 * 2;
                *(float2*)&S[r0 * SSTR + col]       = make_float2(acc[mi][nt][0], acc[mi][nt][1]);
                *(float2*)&S[(r0 + 8) * SSTR + col] = make_float2(acc[mi][nt][2], acc[mi][nt][3]);
            }
        }
    }
    __syncthreads();

    // --- possum_i -> unsim_i ---
    for (int i = wid; i < n; i += 16) {
        float ps = 0.f;
        for (int j = lane; j < n; j += 32)
            if (j != i) ps += ex2f(S[i * SSTR + j]);
        #pragma unroll
        for (int o = 16; o > 0; o >>= 1) ps += __shfl_xor_sync(0xffffffffu, ps, o);
        if (lane == 0) unsimS[i] = g_rowTot[gidx[i]] - ps;
    }
    __syncthreads();

    // --- loss terms ---
    float la = 0.f;
    const int nn = n * n;
    for (int p = tid; p < nn; p += 512) {
        int i = p / n, j = p - i * n;
        if (i == j) continue;
        float s = S[i * SSTR + j];
        la += lg2f(ex2f(s) + unsimS[i]) - s;
    }
    tr[tid] = la * LN2F;
    __syncthreads();
    #pragma unroll
    for (int o = 256; o > 0; o >>= 1) {
        if (tid < o) tr[tid] += tr[tid + o];
        __syncthreads();
    }
    if (tid == 0) {
        g_classLoss[c] = tr[0];
        g_classN[c] = (float)n * (float)(n - 1);
        __threadfence();
        isLast = (atomicAdd(&g_done, 1) == NCLS - 1);
    }
    __syncthreads();
    if (isLast) {
        __threadfence();
        float L = 0.f, P = 0.f;
        if (tid < NCLS) { L = g_classLoss[tid]; P = g_classN[tid]; }
        tr[tid] = L;
        tp[tid] = P;
        __syncthreads();
        #pragma unroll
        for (int o = 64; o > 0; o >>= 1) {
            if (tid < o) { tr[tid] += tr[tid + o]; tp[tid] += tp[tid + o]; }
            __syncthreads();
        }
        if (tid == 0) {
            out[0] = tr[0] / tp[0];
            g_done = 0;   // reset for next graph replay
        }
    }
}

// ---------------- launch ----------------
extern "C" void kernel_launch(void* const* d_in, const int* in_sizes, int n_in,
                              void* d_out, int out_size) {
    const float* x     = (const float*)d_in[0];
    const int*   label = (const int*)d_in[1];
    float*       out   = (float*)d_out;

    cudaFuncSetAttribute(gram_hmma, cudaFuncAttributeMaxDynamicSharedMemorySize, SM_TOTAL);
    cudaFuncSetAttribute(class_loss_kernel, cudaFuncAttributeMaxDynamicSharedMemorySize, CLS_SMEM);

    prep_kernel<<<N / 16, 256>>>(x);
    gram_hmma<<<NBLK, 256, SM_TOTAL>>>();
    class_loss_kernel<<<NCLS, 512, CLS_SMEM>>>(label, out);
}